// round 13
// baseline (speedup 1.0000x reference)
#include <cuda_runtime.h>
#include <cuda_bf16.h>
#include <math.h>

#define BB 4
#define SSZ 1024
#define DDIM 1024
#define NH 16
#define HD 64
#define FF 2048
#define HID 4096
#define MTOT (BB*SSZ)   // 4096

// ---------------- scratch (static device globals; no allocation) ----------------
__device__ float g_q[MTOT*DDIM];
__device__ float g_k[MTOT*DDIM];
__device__ float g_v[MTOT*DDIM];
__device__ float g_sc[67108864];          // [B*NH, S, S]
__device__ float g_attn[MTOT*DDIM];
__device__ float g_tmp[MTOT*DDIM];
__device__ float g_h[MTOT*DDIM];
__device__ float g_ffn[MTOT*FF];
__device__ float g_feat[MTOT*DDIM];
__device__ float g_feat2[MTOT*DDIM];
__device__ float g_sv[MTOT];
__device__ float g_kb2[MTOT];
__device__ int   g_seg[MTOT];
__device__ float g_pool[MTOT*DDIM];
__device__ float g_ph[16777216];          // [MTOT, HID]
__device__ float g_wqkv[DDIM*3*DDIM];     // [1024, 3072] concat weights
__device__ float g_bqkv[3*DDIM];

// ---------------- helpers ----------------
__device__ __forceinline__ float gelu_exact(float x) {
    return 0.5f * x * (1.0f + erff(x * 0.70710678118654752440f));
}

// packed f32x2: two independent IEEE fp32 FMAs per instruction (sm_103a FFMA2)
__device__ __forceinline__ unsigned long long dup_f32x2(float a) {
    unsigned u = __float_as_uint(a);
    unsigned long long r;
    asm("mov.b64 %0, {%1, %2};" : "=l"(r) : "r"(u), "r"(u));
    return r;
}
__device__ __forceinline__ void fma_f32x2(unsigned long long& d,
                                          unsigned long long a, unsigned long long b) {
    asm("fma.rn.f32x2 %0, %1, %2, %0;" : "+l"(d) : "l"(a), "l"(b));
}
__device__ __forceinline__ void unpack_f32x2(unsigned long long p, float& lo, float& hi) {
    unsigned ulo, uhi;
    asm("mov.b64 {%0, %1}, %2;" : "=r"(ulo), "=r"(uhi) : "l"(p));
    lo = __uint_as_float(ulo); hi = __uint_as_float(uhi);
}

__device__ __forceinline__ float blk_sum(float v) {
    __shared__ float sh[8];
    int lane = threadIdx.x & 31, w = threadIdx.x >> 5;
    #pragma unroll
    for (int o = 16; o; o >>= 1) v += __shfl_xor_sync(0xffffffffu, v, o);
    if (lane == 0) sh[w] = v;
    __syncthreads();
    if (threadIdx.x < 32) {
        float t = (lane < 8) ? sh[lane] : 0.0f;
        #pragma unroll
        for (int o = 4; o; o >>= 1) t += __shfl_xor_sync(0xffffffffu, t, o);
        if (lane == 0) sh[0] = t;
    }
    __syncthreads();
    float r = sh[0];
    __syncthreads();
    return r;
}

__device__ __forceinline__ float blk_max(float v) {
    __shared__ float sh[8];
    int lane = threadIdx.x & 31, w = threadIdx.x >> 5;
    #pragma unroll
    for (int o = 16; o; o >>= 1) v = fmaxf(v, __shfl_xor_sync(0xffffffffu, v, o));
    if (lane == 0) sh[w] = v;
    __syncthreads();
    if (threadIdx.x < 32) {
        float t = (lane < 8) ? sh[lane] : -3.4e38f;
        #pragma unroll
        for (int o = 4; o; o >>= 1) t = fmaxf(t, __shfl_xor_sync(0xffffffffu, t, o));
        if (lane == 0) sh[0] = t;
    }
    __syncthreads();
    float r = sh[0];
    __syncthreads();
    return r;
}

// ---------------- concat [Wq|Wk|Wv] and biases ----------------
__global__ void concat_qkv(const float* __restrict__ Wq, const float* __restrict__ Wk,
                           const float* __restrict__ Wv, const float* __restrict__ bq,
                           const float* __restrict__ bk, const float* __restrict__ bv,
                           float* __restrict__ Wc, float* __restrict__ bc) {
    int i = blockIdx.x * 256 + threadIdx.x;
    int r = i / 3072, c = i % 3072;
    float val;
    if (c < 1024)      val = Wq[r * 1024 + c];
    else if (c < 2048) val = Wk[r * 1024 + (c - 1024)];
    else               val = Wv[r * 1024 + (c - 2048)];
    Wc[i] = val;
    if (i < 3072)
        bc[i] = (i < 1024) ? bq[i] : (i < 2048) ? bk[i - 1024] : bv[i - 2048];
}

// ---------------- fp32 GEMM: 64x128 tile, 3 CTAs/SM, FFMA2 ----------------
// Per-output fmaf chain identical to all passing rounds: k ascending, chunks of
// 8, kk inner ascending. QKV3: N==3072 with per-block routing into q/k/v.
template<int ACT, int QKV3>
__global__ void __launch_bounds__(256, 3)
gemm64(const float* __restrict__ A, const float* __restrict__ B,
       const float* __restrict__ bias, float* __restrict__ C0,
       float* __restrict__ C1, float* __restrict__ C2,
       int M, int N, int K) {
    __shared__ float As[2][8][64];
    __shared__ float Bs[2][8][128];
    int tid = threadIdx.x;
    int col0 = blockIdx.x * 128, row0 = blockIdx.y * 64;
    int tx = tid & 15, ty = tid >> 4;
    int ar = tid >> 1, ac = (tid & 1) * 4;   // A loader (tid<128): 64 rows x 8 k
    int br = tid >> 5, bc = (tid & 31) * 4;  // B loader: 8 k x 128 cols
    const float* Aptr = A + (size_t)(row0 + ar) * K + ac;
    const float* Bptr = B + (size_t)br * N + col0 + bc;
    unsigned long long acc2[4][4];
    #pragma unroll
    for (int i = 0; i < 4; i++)
        #pragma unroll
        for (int jp = 0; jp < 4; jp++) acc2[i][jp] = 0ULL;

    if (tid < 128) {
        float4 av = *(const float4*)Aptr;
        As[0][ac + 0][ar] = av.x; As[0][ac + 1][ar] = av.y;
        As[0][ac + 2][ar] = av.z; As[0][ac + 3][ar] = av.w;
    }
    {
        float4 bv = *(const float4*)Bptr;
        *(float4*)&Bs[0][br][bc] = bv;
    }
    __syncthreads();

    int cur = 0;
    for (int k0 = 0; k0 < K; k0 += 8) {
        bool has = (k0 + 8 < K);
        float4 av2, bv2;
        if (has) {
            if (tid < 128) av2 = *(const float4*)(Aptr + k0 + 8);
            bv2 = *(const float4*)(Bptr + (size_t)(k0 + 8) * N);
        }
        #pragma unroll
        for (int kk = 0; kk < 8; kk++) {
            float4 a4 = *(const float4*)&As[cur][kk][ty * 4];
            ulonglong2 q0v = *(const ulonglong2*)&Bs[cur][kk][tx * 8];
            ulonglong2 q1v = *(const ulonglong2*)&Bs[cur][kk][tx * 8 + 4];
            unsigned long long bq[4] = {q0v.x, q0v.y, q1v.x, q1v.y};
            unsigned long long ad[4] = {dup_f32x2(a4.x), dup_f32x2(a4.y),
                                        dup_f32x2(a4.z), dup_f32x2(a4.w)};
            #pragma unroll
            for (int i = 0; i < 4; i++)
                #pragma unroll
                for (int jp = 0; jp < 4; jp++)
                    fma_f32x2(acc2[i][jp], ad[i], bq[jp]);
        }
        if (has) {
            int nb = cur ^ 1;
            if (tid < 128) {
                As[nb][ac + 0][ar] = av2.x; As[nb][ac + 1][ar] = av2.y;
                As[nb][ac + 2][ar] = av2.z; As[nb][ac + 3][ar] = av2.w;
            }
            *(float4*)&Bs[nb][br][bc] = bv2;
        }
        __syncthreads();
        cur ^= 1;
    }

    // epilogue (QKV3: route whole block by col0 segment; boundaries are
    // multiples of 1024 and the 128-wide tile never straddles them)
    float* Cd = C0;
    int cl0 = col0;
    int Nout = N;
    if (QKV3) {
        int seg = col0 >> 10;
        Cd = (seg == 0) ? C0 : (seg == 1) ? C1 : C2;
        cl0 = col0 & 1023;
        Nout = 1024;
    }
    #pragma unroll
    for (int i = 0; i < 4; i++) {
        int r = row0 + ty * 4 + i;
        #pragma unroll
        for (int jp = 0; jp < 4; jp++) {
            float lo, hi;
            unpack_f32x2(acc2[i][jp], lo, hi);
            int gc = col0 + tx * 8 + jp * 2;
            int c  = cl0 + tx * 8 + jp * 2;
            float v0 = lo + bias[gc];
            float v1 = hi + bias[gc + 1];
            if (ACT == 1) { v0 = gelu_exact(v0); v1 = gelu_exact(v1); }
            Cd[(size_t)r * Nout + c]     = v0;
            Cd[(size_t)r * Nout + c + 1] = v1;
        }
    }
}

// ================= bf16 split-precision tensor-core GEMM (projector only) =====
#define GA_PAD 40
#define GB_PAD 136
#define GA_SZ (128*GA_PAD)
#define GB_SZ (32*GB_PAD)

__device__ __forceinline__ void mma16816(float* d, const unsigned* a,
                                         unsigned b0, unsigned b1) {
    asm volatile(
        "mma.sync.aligned.m16n8k16.row.col.f32.bf16.bf16.f32 "
        "{%0,%1,%2,%3}, {%4,%5,%6,%7}, {%8,%9}, {%0,%1,%2,%3};"
        : "+f"(d[0]), "+f"(d[1]), "+f"(d[2]), "+f"(d[3])
        : "r"(a[0]), "r"(a[1]), "r"(a[2]), "r"(a[3]), "r"(b0), "r"(b1));
}

__device__ __forceinline__ void ldsm4(unsigned* r, const __nv_bfloat16* p) {
    unsigned addr = (unsigned)__cvta_generic_to_shared(p);
    asm volatile("ldmatrix.sync.aligned.m8n8.x4.shared.b16 {%0,%1,%2,%3}, [%4];"
                 : "=r"(r[0]), "=r"(r[1]), "=r"(r[2]), "=r"(r[3]) : "r"(addr));
}

__device__ __forceinline__ void ldsm4t(unsigned* r, const __nv_bfloat16* p) {
    unsigned addr = (unsigned)__cvta_generic_to_shared(p);
    asm volatile("ldmatrix.sync.aligned.m8n8.x4.trans.shared.b16 {%0,%1,%2,%3}, [%4];"
                 : "=r"(r[0]), "=r"(r[1]), "=r"(r[2]), "=r"(r[3]) : "r"(addr));
}

template<int SPLITS, int ACT>
__global__ void __launch_bounds__(256, 2)
gemm_mma(const float* __restrict__ A, const float* __restrict__ B,
         const float* __restrict__ bias, float* __restrict__ C,
         int M, int N, int K) {
    extern __shared__ __nv_bfloat16 smbuf[];
    __nv_bfloat16* Ah = smbuf;
    __nv_bfloat16* Bh = smbuf + SPLITS * GA_SZ;

    const int tid = threadIdx.x;
    const int lane = tid & 31, w = tid >> 5;
    const int wm = w & 3, wn = w >> 2;
    const int row0 = blockIdx.y * 128, col0 = blockIdx.x * 128;

    float d[2][8][4];
    #pragma unroll
    for (int i = 0; i < 2; i++)
        #pragma unroll
        for (int j = 0; j < 8; j++)
            #pragma unroll
            for (int c = 0; c < 4; c++) d[i][j][c] = 0.0f;

    const int NC = (SPLITS == 3) ? 6 : 3;
    const int SA[6] = {0, 0, 1, 1, 0, 2};
    const int SB[6] = {0, 1, 0, 1, 2, 0};

    const int a_row = wm * 32 + (lane & 15);
    const int a_kof = (lane >> 4) << 3;
    const int b_kof = ((lane >> 3) & 1) * 8 + (lane & 7);
    const int b_nof = wn * 64 + (lane >> 4) * 8;

    for (int k0 = 0; k0 < K; k0 += 32) {
        #pragma unroll
        for (int it = 0; it < 4; it++) {
            int m = (tid >> 3) + it * 32;
            int kk = (tid & 7) * 4;
            float4 v4 = *(const float4*)(A + (size_t)(row0 + m) * K + k0 + kk);
            float r[4] = {v4.x, v4.y, v4.z, v4.w};
            __nv_bfloat16* dst = Ah + m * GA_PAD + kk;
            #pragma unroll
            for (int s = 0; s < SPLITS; s++) {
                __nv_bfloat16 b0 = __float2bfloat16(r[0]);
                __nv_bfloat16 b1 = __float2bfloat16(r[1]);
                __nv_bfloat16 b2 = __float2bfloat16(r[2]);
                __nv_bfloat16 b3 = __float2bfloat16(r[3]);
                if (s + 1 < SPLITS) {
                    r[0] -= __bfloat162float(b0); r[1] -= __bfloat162float(b1);
                    r[2] -= __bfloat162float(b2); r[3] -= __bfloat162float(b3);
                }
                __nv_bfloat162 p0; p0.x = b0; p0.y = b1;
                __nv_bfloat162 p1; p1.x = b2; p1.y = b3;
                *(__nv_bfloat162*)(dst + s * GA_SZ)     = p0;
                *(__nv_bfloat162*)(dst + s * GA_SZ + 2) = p1;
            }
        }
        #pragma unroll
        for (int it = 0; it < 4; it++) {
            int kk = (tid >> 5) + it * 8;
            int n  = (tid & 31) * 4;
            float4 v4 = *(const float4*)(B + (size_t)(k0 + kk) * N + col0 + n);
            float r[4] = {v4.x, v4.y, v4.z, v4.w};
            __nv_bfloat16* dst = Bh + kk * GB_PAD + n;
            #pragma unroll
            for (int s = 0; s < SPLITS; s++) {
                __nv_bfloat16 b0 = __float2bfloat16(r[0]);
                __nv_bfloat16 b1 = __float2bfloat16(r[1]);
                __nv_bfloat16 b2 = __float2bfloat16(r[2]);
                __nv_bfloat16 b3 = __float2bfloat16(r[3]);
                if (s + 1 < SPLITS) {
                    r[0] -= __bfloat162float(b0); r[1] -= __bfloat162float(b1);
                    r[2] -= __bfloat162float(b2); r[3] -= __bfloat162float(b3);
                }
                __nv_bfloat162 p0; p0.x = b0; p0.y = b1;
                __nv_bfloat162 p1; p1.x = b2; p1.y = b3;
                *(__nv_bfloat162*)(dst + s * GB_SZ)     = p0;
                *(__nv_bfloat162*)(dst + s * GB_SZ + 2) = p1;
            }
        }
        __syncthreads();

        #pragma unroll
        for (int kk = 0; kk < 32; kk += 16) {
            unsigned afr[3][2][4];
            #pragma unroll
            for (int s = 0; s < SPLITS; s++)
                #pragma unroll
                for (int mt = 0; mt < 2; mt++)
                    ldsm4(afr[s][mt],
                          Ah + s * GA_SZ + (a_row + mt * 16) * GA_PAD + kk + a_kof);
            #pragma unroll
            for (int nt4 = 0; nt4 < 4; nt4++) {
                unsigned bfr[3][4];
                #pragma unroll
                for (int s = 0; s < SPLITS; s++)
                    ldsm4t(bfr[s],
                           Bh + s * GB_SZ + (kk + b_kof) * GB_PAD + b_nof + nt4 * 16);
                #pragma unroll
                for (int mt = 0; mt < 2; mt++) {
                    #pragma unroll
                    for (int c = 0; c < NC; c++) {
                        mma16816(d[mt][nt4 * 2],     afr[SA[c]][mt], bfr[SB[c]][0], bfr[SB[c]][1]);
                        mma16816(d[mt][nt4 * 2 + 1], afr[SA[c]][mt], bfr[SB[c]][2], bfr[SB[c]][3]);
                    }
                }
            }
        }
        __syncthreads();
    }

    const int g = lane >> 2, l = lane & 3;
    #pragma unroll
    for (int mt = 0; mt < 2; mt++) {
        int r0 = row0 + wm * 32 + mt * 16 + g;
        #pragma unroll
        for (int nt = 0; nt < 8; nt++) {
            int c = col0 + wn * 64 + nt * 8 + 2 * l;
            float bia0 = bias[c], bia1 = bias[c + 1];
            float v0 = d[mt][nt][0] + bia0, v1 = d[mt][nt][1] + bia1;
            float v2 = d[mt][nt][2] + bia0, v3 = d[mt][nt][3] + bia1;
            if (ACT == 1) {
                v0 = gelu_exact(v0); v1 = gelu_exact(v1);
                v2 = gelu_exact(v2); v3 = gelu_exact(v3);
            }
            float2 p0 = {v0, v1}, p1 = {v2, v3};
            *(float2*)(C + (size_t)r0 * N + c) = p0;
            *(float2*)(C + (size_t)(r0 + 8) * N + c) = p1;
        }
    }
}

// ---------------- attention scores (128q x 64k tile, 8x4/thread, FFMA2) -------
#define QS_PITCH 136
#define KS_PITCH 68
#define SCORES_SMEM ((64*QS_PITCH + 64*KS_PITCH) * 4)

__global__ void __launch_bounds__(256, 3)
attn_scores(const float* __restrict__ q, const float* __restrict__ k,
            float* __restrict__ sc) {
    extern __shared__ float smf[];
    float* qs = smf;                  // [64][136]
    float* ks = smf + 64 * QS_PITCH;  // [64][68]

    int z = blockIdx.z, b = z / NH, h = z % NH;
    int k0 = blockIdx.x * 64, q0 = blockIdx.y * 128;
    int tid = threadIdx.x;

    {
        int row = tid >> 1;
        int hb = (tid & 1) * 32;
        const float* qp = q + (size_t)(b * SSZ + q0 + row) * DDIM + h * HD + hb;
        #pragma unroll
        for (int u = 0; u < 8; u++) {
            float4 v4 = *(const float4*)(qp + u * 4);
            qs[(hb + u * 4 + 0) * QS_PITCH + row] = v4.x;
            qs[(hb + u * 4 + 1) * QS_PITCH + row] = v4.y;
            qs[(hb + u * 4 + 2) * QS_PITCH + row] = v4.z;
            qs[(hb + u * 4 + 3) * QS_PITCH + row] = v4.w;
        }
    }
    {
        int row = tid >> 2;
        int hb = (tid & 3) * 16;
        const float* kp = k + (size_t)(b * SSZ + k0 + row) * DDIM + h * HD + hb;
        #pragma unroll
        for (int u = 0; u < 4; u++) {
            float4 w4 = *(const float4*)(kp + u * 4);
            ks[(hb + u * 4 + 0) * KS_PITCH + row] = w4.x;
            ks[(hb + u * 4 + 1) * KS_PITCH + row] = w4.y;
            ks[(hb + u * 4 + 2) * KS_PITCH + row] = w4.z;
            ks[(hb + u * 4 + 3) * KS_PITCH + row] = w4.w;
        }
    }
    __syncthreads();

    int tx = tid & 15, ty = tid >> 4;
    unsigned long long acc2[8][2];
    #pragma unroll
    for (int i = 0; i < 8; i++) { acc2[i][0] = 0ULL; acc2[i][1] = 0ULL; }

    #pragma unroll 8
    for (int kk = 0; kk < 64; kk++) {
        float4 a0 = *(const float4*)&qs[kk * QS_PITCH + ty * 8];
        float4 a1 = *(const float4*)&qs[kk * QS_PITCH + ty * 8 + 4];
        float af[8] = {a0.x, a0.y, a0.z, a0.w, a1.x, a1.y, a1.z, a1.w};
        ulonglong2 bb = *(const ulonglong2*)&ks[kk * KS_PITCH + tx * 4];
        unsigned long long ad[8];
        #pragma unroll
        for (int i = 0; i < 8; i++) ad[i] = dup_f32x2(af[i]);
        #pragma unroll
        for (int i = 0; i < 8; i++) {
            fma_f32x2(acc2[i][0], ad[i], bb.x);
            fma_f32x2(acc2[i][1], ad[i], bb.y);
        }
    }
    float* out = sc + (size_t)z * SSZ * SSZ;
    #pragma unroll
    for (int i = 0; i < 8; i++) {
        #pragma unroll
        for (int jp = 0; jp < 2; jp++) {
            float lo, hi;
            unpack_f32x2(acc2[i][jp], lo, hi);
            out[(size_t)(q0 + ty * 8 + i) * SSZ + k0 + tx * 4 + jp * 2]     = lo * 0.125f;
            out[(size_t)(q0 + ty * 8 + i) * SSZ + k0 + tx * 4 + jp * 2 + 1] = hi * 0.125f;
        }
    }
}

// ---------------- softmax over keys with per-(b,key) bias ----------------
__global__ void softmax_rows(float* __restrict__ sc, const float* __restrict__ kb) {
    int row = blockIdx.x;
    int b = row / (NH * SSZ);
    float* p = sc + (size_t)row * SSZ;
    const float* kbp = kb + b * SSZ;
    int tid = threadIdx.x;
    float v[4]; float mx = -3.4e38f;
    #pragma unroll
    for (int u = 0; u < 4; u++) {
        int c = u * 256 + tid;
        v[u] = p[c] + kbp[c];
        mx = fmaxf(mx, v[u]);
    }
    mx = blk_max(mx);
    float s = 0.0f;
    #pragma unroll
    for (int u = 0; u < 4; u++) { v[u] = expf(v[u] - mx); s += v[u]; }
    s = blk_sum(s);
    float inv = 1.0f / s;
    #pragma unroll
    for (int u = 0; u < 4; u++) p[u * 256 + tid] = v[u] * inv;
}

// ---------------- AV (128q x 64hd tile, 8x4/thread, FFMA2) ----------------
__global__ void __launch_bounds__(256, 3)
attn_av(const float* __restrict__ sc, const float* __restrict__ v,
        float* __restrict__ o) {
    __shared__ float As[16][QS_PITCH];
    __shared__ float Bs[16][KS_PITCH];
    int z = blockIdx.y, b = z / NH, h = z % NH;
    int q0 = blockIdx.x * 128;
    const float* Ab = sc + (size_t)z * SSZ * SSZ;
    const float* Vb = v + (size_t)b * SSZ * DDIM + h * HD;
    int tid = threadIdx.x;
    int ar = tid >> 1, ac = (tid & 1) * 8;
    int br = tid >> 4, bc = (tid & 15) * 4;
    int tx = tid & 15, ty = tid >> 4;
    unsigned long long acc2[8][2];
    #pragma unroll
    for (int i = 0; i < 8; i++) { acc2[i][0] = 0ULL; acc2[i][1] = 0ULL; }

    for (int k0 = 0; k0 < SSZ; k0 += 16) {
        const float* ap = Ab + (size_t)(q0 + ar) * SSZ + k0 + ac;
        float4 a4 = *(const float4*)ap;
        float4 a5 = *(const float4*)(ap + 4);
        As[ac + 0][ar] = a4.x; As[ac + 1][ar] = a4.y;
        As[ac + 2][ar] = a4.z; As[ac + 3][ar] = a4.w;
        As[ac + 4][ar] = a5.x; As[ac + 5][ar] = a5.y;
        As[ac + 6][ar] = a5.z; As[ac + 7][ar] = a5.w;
        float4 b4 = *(const float4*)(Vb + (size_t)(k0 + br) * DDIM + bc);
        *(float4*)&Bs[br][bc] = b4;
        __syncthreads();
        #pragma unroll
        for (int kk = 0; kk < 16; kk++) {
            float4 a0 = *(const float4*)&As[kk][ty * 8];
            float4 a1 = *(const float4*)&As[kk][ty * 8 + 4];
            float af[8] = {a0.x, a0.y, a0.z, a0.w, a1.x, a1.y, a1.z, a1.w};
            ulonglong2 bb = *(const ulonglong2*)&Bs[kk][tx * 4];
            unsigned long long ad[8];
            #pragma unroll
            for (int i = 0; i < 8; i++) ad[i] = dup_f32x2(af[i]);
            #pragma unroll
            for (int i = 0; i < 8; i++) {
                fma_f32x2(acc2[i][0], ad[i], bb.x);
                fma_f32x2(acc2[i][1], ad[i], bb.y);
            }
        }
        __syncthreads();
    }
    float* Ob = o + (size_t)(b * SSZ + q0) * DDIM + h * HD;
    #pragma unroll
    for (int i = 0; i < 8; i++) {
        #pragma unroll
        for (int jp = 0; jp < 2; jp++) {
            float lo, hi;
            unpack_f32x2(acc2[i][jp], lo, hi);
            Ob[(size_t)(ty * 8 + i) * DDIM + tx * 4 + jp * 2]     = lo;
            Ob[(size_t)(ty * 8 + i) * DDIM + tx * 4 + jp * 2 + 1] = hi;
        }
    }
}

// ---------------- residual add + LayerNorm ----------------
__global__ void add_ln(const float* __restrict__ x, const float* __restrict__ y,
                       const float* __restrict__ g, const float* __restrict__ be,
                       float* __restrict__ out) {
    int row = blockIdx.x, tid = threadIdx.x;
    const float* xp = x + (size_t)row * DDIM;
    const float* yp = y + (size_t)row * DDIM;
    float v[4]; float s = 0.0f;
    #pragma unroll
    for (int u = 0; u < 4; u++) {
        int c = u * 256 + tid;
        v[u] = xp[c] + yp[c];
        s += v[u];
    }
    s = blk_sum(s);
    float mean = s * (1.0f / DDIM);
    float qv = 0.0f;
    #pragma unroll
    for (int u = 0; u < 4; u++) { float dd = v[u] - mean; qv += dd * dd; }
    qv = blk_sum(qv);
    float rstd = rsqrtf(qv * (1.0f / DDIM) + 1e-5f);
    float* op = out + (size_t)row * DDIM;
    #pragma unroll
    for (int u = 0; u < 4; u++) {
        int c = u * 256 + tid;
        op[c] = (v[u] - mean) * rstd * g[c] + be[c];
    }
}

// ---------------- importance score head ----------------
__global__ void score_head(const float* __restrict__ f, const float* __restrict__ Ws,
                           const float* __restrict__ bsc, const float* __restrict__ masks,
                           float* __restrict__ sv) {
    int row = blockIdx.x, tid = threadIdx.x;
    const float* fp = f + (size_t)row * DDIM;
    float s = 0.0f;
    #pragma unroll
    for (int u = 0; u < 4; u++) {
        int c = u * 256 + tid;
        s += fp[c] * Ws[c];
    }
    s = blk_sum(s);
    if (tid == 0) {
        float val = 1.0f / (1.0f + expf(-(s + bsc[0])));
        sv[row] = (masks[row] > 0.0f) ? val : 0.0f;
    }
}

__global__ void make_kb2(const float* __restrict__ masks, float* __restrict__ kb2) {
    int i = blockIdx.x * 256 + threadIdx.x;
    if (i < MTOT) kb2[i] = (masks[i] > 0.0f) ? 0.0f : -1e9f;
}

// ---------------- sequential scan per batch ----------------
__global__ void scan_kernel(const float* __restrict__ sv, const float* __restrict__ masks,
                            int* __restrict__ seg, float* __restrict__ mask_out) {
    int b = threadIdx.x;
    if (b >= BB) return;
    float c = 0.0f, maxseg = -1.0f;
    for (int t = 0; t < SSZ; t++) {
        c = c + sv[b * SSZ + t];
        float cf = floorf(c);
        int sg = (int)cf;
        if (sg > SSZ - 1) sg = SSZ - 1;
        if (sg < 0) sg = 0;
        seg[b * SSZ + t] = sg;
        if (masks[b * SSZ + t] > 0.0f) maxseg = fmaxf(maxseg, cf);
    }
    for (int t = 0; t < SSZ; t++)
        mask_out[b * SSZ + t] = ((float)t <= maxseg) ? 1.0f : 0.0f;
}

__global__ void zero_pool(float* __restrict__ p) {
    size_t i = (size_t)blockIdx.x * 256 + threadIdx.x;
    if (i < (size_t)MTOT * DDIM) p[i] = 0.0f;
}

__global__ void seg_pool(const float* __restrict__ x, const float* __restrict__ sv,
                         const int* __restrict__ seg, float* __restrict__ pooled) {
    int b = blockIdx.y;
    int dcol = blockIdx.x * 256 + threadIdx.x;
    __shared__ float svs[SSZ];
    __shared__ int sgs[SSZ];
    for (int t = threadIdx.x; t < SSZ; t += 256) {
        svs[t] = sv[b * SSZ + t];
        sgs[t] = seg[b * SSZ + t];
    }
    __syncthreads();
    const float* xb = x + (size_t)b * SSZ * DDIM + dcol;
    float acc = 0.0f;
    int cur = sgs[0];
    for (int t = 0; t < SSZ; t++) {
        int sg = sgs[t];
        if (sg != cur) {
            pooled[((size_t)b * SSZ + cur) * DDIM + dcol] = acc;
            acc = 0.0f;
            cur = sg;
        }
        acc = fmaf(xb[(size_t)t * DDIM], svs[t], acc);
    }
    pooled[((size_t)b * SSZ + cur) * DDIM + dcol] = acc;
}

// ---------------- host ----------------
extern "C" void kernel_launch(void* const* d_in, const int* in_sizes, int n_in,
                              void* d_out, int out_size) {
    const float* x     = (const float*)d_in[0];
    const float* masks = (const float*)d_in[1];
    const float* Wq = (const float*)d_in[2];  const float* bq = (const float*)d_in[3];
    const float* Wk = (const float*)d_in[4];  const float* bk = (const float*)d_in[5];
    const float* Wv = (const float*)d_in[6];  const float* bv = (const float*)d_in[7];
    const float* Wo = (const float*)d_in[8];  const float* bo = (const float*)d_in[9];
    const float* g1 = (const float*)d_in[10]; const float* be1 = (const float*)d_in[11];
    const float* g2 = (const float*)d_in[12]; const float* be2 = (const float*)d_in[13];
    const float* W1 = (const float*)d_in[14]; const float* bf1 = (const float*)d_in[15];
    const float* W2 = (const float*)d_in[16]; const float* bf2 = (const float*)d_in[17];
    const float* Ws = (const float*)d_in[18]; const float* bs = (const float*)d_in[19];
    const float* P1 = (const float*)d_in[20]; const float* bp1 = (const float*)d_in[21];
    const float* P2 = (const float*)d_in[22]; const float* bp2 = (const float*)d_in[23];
    float* out = (float*)d_out;

    float *q, *k, *v, *sc, *attn, *tmp, *h, *ffn, *feat, *feat2, *sv, *kb2, *pool, *ph;
    float *wqkv, *bqkv;
    int* seg;
    cudaGetSymbolAddress((void**)&q, g_q);
    cudaGetSymbolAddress((void**)&k, g_k);
    cudaGetSymbolAddress((void**)&v, g_v);
    cudaGetSymbolAddress((void**)&sc, g_sc);
    cudaGetSymbolAddress((void**)&attn, g_attn);
    cudaGetSymbolAddress((void**)&tmp, g_tmp);
    cudaGetSymbolAddress((void**)&h, g_h);
    cudaGetSymbolAddress((void**)&ffn, g_ffn);
    cudaGetSymbolAddress((void**)&feat, g_feat);
    cudaGetSymbolAddress((void**)&feat2, g_feat2);
    cudaGetSymbolAddress((void**)&sv, g_sv);
    cudaGetSymbolAddress((void**)&kb2, g_kb2);
    cudaGetSymbolAddress((void**)&seg, g_seg);
    cudaGetSymbolAddress((void**)&pool, g_pool);
    cudaGetSymbolAddress((void**)&ph, g_ph);
    cudaGetSymbolAddress((void**)&wqkv, g_wqkv);
    cudaGetSymbolAddress((void**)&bqkv, g_bqkv);

    const int SM2 = 2 * (GA_SZ + GB_SZ) * 2;   // 37888 bytes
    cudaFuncSetAttribute(gemm_mma<2,0>, cudaFuncAttributeMaxDynamicSharedMemorySize, SM2);
    cudaFuncSetAttribute(gemm_mma<2,1>, cudaFuncAttributeMaxDynamicSharedMemorySize, SM2);
    cudaFuncSetAttribute(attn_scores, cudaFuncAttributeMaxDynamicSharedMemorySize, SCORES_SMEM);

    concat_qkv<<<(DDIM * 3 * DDIM) / 256, 256>>>(Wq, Wk, Wv, bq, bk, bv, wqkv, bqkv);

    auto layer = [&](const float* in, const float* kb, float* outf) {
        gemm64<0,1><<<dim3(3 * DDIM / 128, MTOT / 64), 256>>>(
            in, wqkv, bqkv, q, k, v, MTOT, 3 * DDIM, DDIM);
        dim3 gs(SSZ / 64, SSZ / 128, BB * NH);
        attn_scores<<<gs, 256, SCORES_SMEM>>>(q, k, sc);
        softmax_rows<<<BB * NH * SSZ, 256>>>(sc, kb);
        dim3 ga(SSZ / 128, BB * NH);
        attn_av<<<ga, 256>>>(sc, v, attn);
        gemm64<0,0><<<dim3(DDIM / 128, MTOT / 64), 256>>>(
            attn, Wo, bo, tmp, nullptr, nullptr, MTOT, DDIM, DDIM);
        add_ln<<<MTOT, 256>>>(in, tmp, g1, be1, h);
        gemm64<1,0><<<dim3(FF / 128, MTOT / 64), 256>>>(
            h, W1, bf1, ffn, nullptr, nullptr, MTOT, FF, DDIM);
        gemm64<0,0><<<dim3(DDIM / 128, MTOT / 64), 256>>>(
            ffn, W2, bf2, tmp, nullptr, nullptr, MTOT, DDIM, FF);
        add_ln<<<MTOT, 256>>>(h, tmp, g2, be2, outf);
    };

    layer(x, masks, feat);
    make_kb2<<<MTOT / 256, 256>>>(masks, kb2);
    layer(feat, kb2, feat2);

    score_head<<<MTOT, 256>>>(feat2, Ws, bs, masks, sv);
    scan_kernel<<<1, 32>>>(sv, masks, seg, out + (size_t)MTOT * HID);
    zero_pool<<<(MTOT * DDIM) / 256, 256>>>(pool);
    seg_pool<<<dim3(DDIM / 256, BB), 256>>>(x, sv, seg, pool);

    gemm_mma<2,1><<<dim3(HID / 128, MTOT / 128), 256, SM2>>>(pool, P1, bp1, ph, MTOT, HID, DDIM);
    gemm_mma<2,0><<<dim3(HID / 128, MTOT / 128), 256, SM2>>>(ph, P2, bp2, out, MTOT, HID, HID);
}

// round 14
// speedup vs baseline: 1.3115x; 1.3115x over previous
#include <cuda_runtime.h>
#include <cuda_bf16.h>
#include <math.h>

#define BB 4
#define SSZ 1024
#define DDIM 1024
#define NH 16
#define HD 64
#define FF 2048
#define HID 4096
#define MTOT (BB*SSZ)   // 4096

// ---------------- scratch (static device globals; no allocation) ----------------
__device__ float g_q[MTOT*DDIM];
__device__ float g_k[MTOT*DDIM];
__device__ float g_v[MTOT*DDIM];
__device__ float g_sc[67108864];          // [B*NH, S, S]
__device__ float g_attn[MTOT*DDIM];
__device__ float g_tmp[MTOT*DDIM];
__device__ float g_h[MTOT*DDIM];
__device__ float g_ffn[MTOT*FF];
__device__ float g_feat[MTOT*DDIM];
__device__ float g_feat2[MTOT*DDIM];
__device__ float g_sv[MTOT];
__device__ float g_kb2[MTOT];
__device__ int   g_seg[MTOT];
__device__ float g_pool[MTOT*DDIM];
__device__ float g_ph[16777216];          // [MTOT, HID]
__device__ float g_wqkv[DDIM*3*DDIM];     // [1024, 3072] concat weights
__device__ float g_bqkv[3*DDIM];

// ---------------- helpers ----------------
__device__ __forceinline__ float gelu_exact(float x) {
    return 0.5f * x * (1.0f + erff(x * 0.70710678118654752440f));
}

// packed f32x2: two independent IEEE fp32 FMAs per instruction (sm_103a FFMA2)
__device__ __forceinline__ unsigned long long dup_f32x2(float a) {
    unsigned u = __float_as_uint(a);
    unsigned long long r;
    asm("mov.b64 %0, {%1, %2};" : "=l"(r) : "r"(u), "r"(u));
    return r;
}
__device__ __forceinline__ void fma_f32x2(unsigned long long& d,
                                          unsigned long long a, unsigned long long b) {
    asm("fma.rn.f32x2 %0, %1, %2, %0;" : "+l"(d) : "l"(a), "l"(b));
}
__device__ __forceinline__ void unpack_f32x2(unsigned long long p, float& lo, float& hi) {
    unsigned ulo, uhi;
    asm("mov.b64 {%0, %1}, %2;" : "=r"(ulo), "=r"(uhi) : "l"(p));
    lo = __uint_as_float(ulo); hi = __uint_as_float(uhi);
}

__device__ __forceinline__ float blk_sum(float v) {
    __shared__ float sh[8];
    int lane = threadIdx.x & 31, w = threadIdx.x >> 5;
    #pragma unroll
    for (int o = 16; o; o >>= 1) v += __shfl_xor_sync(0xffffffffu, v, o);
    if (lane == 0) sh[w] = v;
    __syncthreads();
    if (threadIdx.x < 32) {
        float t = (lane < 8) ? sh[lane] : 0.0f;
        #pragma unroll
        for (int o = 4; o; o >>= 1) t += __shfl_xor_sync(0xffffffffu, t, o);
        if (lane == 0) sh[0] = t;
    }
    __syncthreads();
    float r = sh[0];
    __syncthreads();
    return r;
}

__device__ __forceinline__ float blk_max(float v) {
    __shared__ float sh[8];
    int lane = threadIdx.x & 31, w = threadIdx.x >> 5;
    #pragma unroll
    for (int o = 16; o; o >>= 1) v = fmaxf(v, __shfl_xor_sync(0xffffffffu, v, o));
    if (lane == 0) sh[w] = v;
    __syncthreads();
    if (threadIdx.x < 32) {
        float t = (lane < 8) ? sh[lane] : -3.4e38f;
        #pragma unroll
        for (int o = 4; o; o >>= 1) t = fmaxf(t, __shfl_xor_sync(0xffffffffu, t, o));
        if (lane == 0) sh[0] = t;
    }
    __syncthreads();
    float r = sh[0];
    __syncthreads();
    return r;
}

// ---------------- concat [Wq|Wk|Wv] and biases ----------------
__global__ void concat_qkv(const float* __restrict__ Wq, const float* __restrict__ Wk,
                           const float* __restrict__ Wv, const float* __restrict__ bq,
                           const float* __restrict__ bk, const float* __restrict__ bv,
                           float* __restrict__ Wc, float* __restrict__ bc) {
    int i = blockIdx.x * 256 + threadIdx.x;
    int r = i / 3072, c = i % 3072;
    float val;
    if (c < 1024)      val = Wq[r * 1024 + c];
    else if (c < 2048) val = Wk[r * 1024 + (c - 1024)];
    else               val = Wv[r * 1024 + (c - 2048)];
    Wc[i] = val;
    if (i < 3072)
        bc[i] = (i < 1024) ? bq[i] : (i < 2048) ? bk[i - 1024] : bv[i - 2048];
}

// ---------------- fp32 GEMM (128x128, double-buffered, FFMA2) ----------------
// Per-output fmaf chain identical to R2/R4: k ascending, lane-independent FFMA2.
// QKV3: N==3072 with per-128-col-block routing into q/k/v (boundaries at 1024).
template<int ACT, int QKV3>
__global__ void __launch_bounds__(256, 2)
gemm128(const float* __restrict__ A, const float* __restrict__ B,
        const float* __restrict__ bias, float* __restrict__ C0,
        float* __restrict__ C1, float* __restrict__ C2,
        int M, int N, int K) {
    __shared__ float As[2][8][128];
    __shared__ float Bs[2][8][128];
    int tid = threadIdx.x;
    int col0 = blockIdx.x * 128, row0 = blockIdx.y * 128;
    int tx = tid & 15, ty = tid >> 4;
    int ar = tid >> 1, ac = (tid & 1) * 4;
    int br = tid >> 5, bc = (tid & 31) * 4;
    const float* Aptr = A + (size_t)(row0 + ar) * K + ac;
    const float* Bptr = B + (size_t)br * N + col0 + bc;
    unsigned long long acc2[8][4];   // acc2[i][jp] = (acc[i][2jp], acc[i][2jp+1])
    #pragma unroll
    for (int i = 0; i < 8; i++)
        #pragma unroll
        for (int jp = 0; jp < 4; jp++) acc2[i][jp] = 0ULL;

    {
        float4 av = *(const float4*)Aptr;
        As[0][ac + 0][ar] = av.x; As[0][ac + 1][ar] = av.y;
        As[0][ac + 2][ar] = av.z; As[0][ac + 3][ar] = av.w;
        float4 bv = *(const float4*)Bptr;
        *(float4*)&Bs[0][br][bc] = bv;
    }
    __syncthreads();

    int cur = 0;
    for (int k0 = 0; k0 < K; k0 += 8) {
        bool has = (k0 + 8 < K);
        float4 av2, bv2;
        if (has) {
            av2 = *(const float4*)(Aptr + k0 + 8);
            bv2 = *(const float4*)(Bptr + (size_t)(k0 + 8) * N);
        }
        #pragma unroll
        for (int kk = 0; kk < 8; kk++) {
            float4 a0 = *(const float4*)&As[cur][kk][ty * 8];
            float4 a1 = *(const float4*)&As[cur][kk][ty * 8 + 4];
            float af[8] = {a0.x, a0.y, a0.z, a0.w, a1.x, a1.y, a1.z, a1.w};
            const ulonglong2* bp = (const ulonglong2*)&Bs[cur][kk][tx * 8];
            ulonglong2 bq0 = bp[0], bq1 = bp[1];
            unsigned long long bq[4] = {bq0.x, bq0.y, bq1.x, bq1.y};
            unsigned long long ad[8];
            #pragma unroll
            for (int i = 0; i < 8; i++) ad[i] = dup_f32x2(af[i]);
            #pragma unroll
            for (int i = 0; i < 8; i++)
                #pragma unroll
                for (int jp = 0; jp < 4; jp++)
                    fma_f32x2(acc2[i][jp], ad[i], bq[jp]);
        }
        if (has) {
            int nb = cur ^ 1;
            As[nb][ac + 0][ar] = av2.x; As[nb][ac + 1][ar] = av2.y;
            As[nb][ac + 2][ar] = av2.z; As[nb][ac + 3][ar] = av2.w;
            *(float4*)&Bs[nb][br][bc] = bv2;
        }
        __syncthreads();
        cur ^= 1;
    }

    float* Cd = C0;
    int cl0 = col0;
    int Nout = N;
    if (QKV3) {
        int seg = col0 >> 10;
        Cd = (seg == 0) ? C0 : (seg == 1) ? C1 : C2;
        cl0 = col0 & 1023;
        Nout = 1024;
    }
    #pragma unroll
    for (int i = 0; i < 8; i++) {
        int r = row0 + ty * 8 + i;
        #pragma unroll
        for (int jp = 0; jp < 4; jp++) {
            float lo, hi;
            unpack_f32x2(acc2[i][jp], lo, hi);
            int gc = col0 + tx * 8 + jp * 2;
            int c  = cl0 + tx * 8 + jp * 2;
            float v0 = lo + bias[gc];
            float v1 = hi + bias[gc + 1];
            if (ACT == 1) { v0 = gelu_exact(v0); v1 = gelu_exact(v1); }
            Cd[(size_t)r * Nout + c]     = v0;
            Cd[(size_t)r * Nout + c + 1] = v1;
        }
    }
}

// ================= bf16 split-precision tensor-core GEMM (projector only) =====
#define GA_PAD 40
#define GB_PAD 136
#define GA_SZ (128*GA_PAD)
#define GB_SZ (32*GB_PAD)

__device__ __forceinline__ void mma16816(float* d, const unsigned* a,
                                         unsigned b0, unsigned b1) {
    asm volatile(
        "mma.sync.aligned.m16n8k16.row.col.f32.bf16.bf16.f32 "
        "{%0,%1,%2,%3}, {%4,%5,%6,%7}, {%8,%9}, {%0,%1,%2,%3};"
        : "+f"(d[0]), "+f"(d[1]), "+f"(d[2]), "+f"(d[3])
        : "r"(a[0]), "r"(a[1]), "r"(a[2]), "r"(a[3]), "r"(b0), "r"(b1));
}

__device__ __forceinline__ void ldsm4(unsigned* r, const __nv_bfloat16* p) {
    unsigned addr = (unsigned)__cvta_generic_to_shared(p);
    asm volatile("ldmatrix.sync.aligned.m8n8.x4.shared.b16 {%0,%1,%2,%3}, [%4];"
                 : "=r"(r[0]), "=r"(r[1]), "=r"(r[2]), "=r"(r[3]) : "r"(addr));
}

__device__ __forceinline__ void ldsm4t(unsigned* r, const __nv_bfloat16* p) {
    unsigned addr = (unsigned)__cvta_generic_to_shared(p);
    asm volatile("ldmatrix.sync.aligned.m8n8.x4.trans.shared.b16 {%0,%1,%2,%3}, [%4];"
                 : "=r"(r[0]), "=r"(r[1]), "=r"(r[2]), "=r"(r[3]) : "r"(addr));
}

template<int SPLITS, int ACT>
__global__ void __launch_bounds__(256, 2)
gemm_mma(const float* __restrict__ A, const float* __restrict__ B,
         const float* __restrict__ bias, float* __restrict__ C,
         int M, int N, int K) {
    extern __shared__ __nv_bfloat16 smbuf[];
    __nv_bfloat16* Ah = smbuf;
    __nv_bfloat16* Bh = smbuf + SPLITS * GA_SZ;

    const int tid = threadIdx.x;
    const int lane = tid & 31, w = tid >> 5;
    const int wm = w & 3, wn = w >> 2;
    const int row0 = blockIdx.y * 128, col0 = blockIdx.x * 128;

    float d[2][8][4];
    #pragma unroll
    for (int i = 0; i < 2; i++)
        #pragma unroll
        for (int j = 0; j < 8; j++)
            #pragma unroll
            for (int c = 0; c < 4; c++) d[i][j][c] = 0.0f;

    const int NC = (SPLITS == 3) ? 6 : 3;
    const int SA[6] = {0, 0, 1, 1, 0, 2};
    const int SB[6] = {0, 1, 0, 1, 2, 0};

    const int a_row = wm * 32 + (lane & 15);
    const int a_kof = (lane >> 4) << 3;
    const int b_kof = ((lane >> 3) & 1) * 8 + (lane & 7);
    const int b_nof = wn * 64 + (lane >> 4) * 8;

    for (int k0 = 0; k0 < K; k0 += 32) {
        #pragma unroll
        for (int it = 0; it < 4; it++) {
            int m = (tid >> 3) + it * 32;
            int kk = (tid & 7) * 4;
            float4 v4 = *(const float4*)(A + (size_t)(row0 + m) * K + k0 + kk);
            float r[4] = {v4.x, v4.y, v4.z, v4.w};
            __nv_bfloat16* dst = Ah + m * GA_PAD + kk;
            #pragma unroll
            for (int s = 0; s < SPLITS; s++) {
                __nv_bfloat16 b0 = __float2bfloat16(r[0]);
                __nv_bfloat16 b1 = __float2bfloat16(r[1]);
                __nv_bfloat16 b2 = __float2bfloat16(r[2]);
                __nv_bfloat16 b3 = __float2bfloat16(r[3]);
                if (s + 1 < SPLITS) {
                    r[0] -= __bfloat162float(b0); r[1] -= __bfloat162float(b1);
                    r[2] -= __bfloat162float(b2); r[3] -= __bfloat162float(b3);
                }
                __nv_bfloat162 p0; p0.x = b0; p0.y = b1;
                __nv_bfloat162 p1; p1.x = b2; p1.y = b3;
                *(__nv_bfloat162*)(dst + s * GA_SZ)     = p0;
                *(__nv_bfloat162*)(dst + s * GA_SZ + 2) = p1;
            }
        }
        #pragma unroll
        for (int it = 0; it < 4; it++) {
            int kk = (tid >> 5) + it * 8;
            int n  = (tid & 31) * 4;
            float4 v4 = *(const float4*)(B + (size_t)(k0 + kk) * N + col0 + n);
            float r[4] = {v4.x, v4.y, v4.z, v4.w};
            __nv_bfloat16* dst = Bh + kk * GB_PAD + n;
            #pragma unroll
            for (int s = 0; s < SPLITS; s++) {
                __nv_bfloat16 b0 = __float2bfloat16(r[0]);
                __nv_bfloat16 b1 = __float2bfloat16(r[1]);
                __nv_bfloat16 b2 = __float2bfloat16(r[2]);
                __nv_bfloat16 b3 = __float2bfloat16(r[3]);
                if (s + 1 < SPLITS) {
                    r[0] -= __bfloat162float(b0); r[1] -= __bfloat162float(b1);
                    r[2] -= __bfloat162float(b2); r[3] -= __bfloat162float(b3);
                }
                __nv_bfloat162 p0; p0.x = b0; p0.y = b1;
                __nv_bfloat162 p1; p1.x = b2; p1.y = b3;
                *(__nv_bfloat162*)(dst + s * GB_SZ)     = p0;
                *(__nv_bfloat162*)(dst + s * GB_SZ + 2) = p1;
            }
        }
        __syncthreads();

        #pragma unroll
        for (int kk = 0; kk < 32; kk += 16) {
            unsigned afr[3][2][4];
            #pragma unroll
            for (int s = 0; s < SPLITS; s++)
                #pragma unroll
                for (int mt = 0; mt < 2; mt++)
                    ldsm4(afr[s][mt],
                          Ah + s * GA_SZ + (a_row + mt * 16) * GA_PAD + kk + a_kof);
            #pragma unroll
            for (int nt4 = 0; nt4 < 4; nt4++) {
                unsigned bfr[3][4];
                #pragma unroll
                for (int s = 0; s < SPLITS; s++)
                    ldsm4t(bfr[s],
                           Bh + s * GB_SZ + (kk + b_kof) * GB_PAD + b_nof + nt4 * 16);
                #pragma unroll
                for (int mt = 0; mt < 2; mt++) {
                    #pragma unroll
                    for (int c = 0; c < NC; c++) {
                        mma16816(d[mt][nt4 * 2],     afr[SA[c]][mt], bfr[SB[c]][0], bfr[SB[c]][1]);
                        mma16816(d[mt][nt4 * 2 + 1], afr[SA[c]][mt], bfr[SB[c]][2], bfr[SB[c]][3]);
                    }
                }
            }
        }
        __syncthreads();
    }

    const int g = lane >> 2, l = lane & 3;
    #pragma unroll
    for (int mt = 0; mt < 2; mt++) {
        int r0 = row0 + wm * 32 + mt * 16 + g;
        #pragma unroll
        for (int nt = 0; nt < 8; nt++) {
            int c = col0 + wn * 64 + nt * 8 + 2 * l;
            float bia0 = bias[c], bia1 = bias[c + 1];
            float v0 = d[mt][nt][0] + bia0, v1 = d[mt][nt][1] + bia1;
            float v2 = d[mt][nt][2] + bia0, v3 = d[mt][nt][3] + bia1;
            if (ACT == 1) {
                v0 = gelu_exact(v0); v1 = gelu_exact(v1);
                v2 = gelu_exact(v2); v3 = gelu_exact(v3);
            }
            float2 p0 = {v0, v1}, p1 = {v2, v3};
            *(float2*)(C + (size_t)r0 * N + c) = p0;
            *(float2*)(C + (size_t)(r0 + 8) * N + c) = p1;
        }
    }
}

// ---------------- attention scores (128q x 64k tile, 8x4/thread, FFMA2) -------
#define QS_PITCH 136
#define KS_PITCH 68
#define SCORES_SMEM ((64*QS_PITCH + 64*KS_PITCH) * 4)

__global__ void __launch_bounds__(256, 3)
attn_scores(const float* __restrict__ q, const float* __restrict__ k,
            float* __restrict__ sc) {
    extern __shared__ float smf[];
    float* qs = smf;                  // [64][136]
    float* ks = smf + 64 * QS_PITCH;  // [64][68]

    int z = blockIdx.z, b = z / NH, h = z % NH;
    int k0 = blockIdx.x * 64, q0 = blockIdx.y * 128;
    int tid = threadIdx.x;

    {
        int row = tid >> 1;
        int hb = (tid & 1) * 32;
        const float* qp = q + (size_t)(b * SSZ + q0 + row) * DDIM + h * HD + hb;
        #pragma unroll
        for (int u = 0; u < 8; u++) {
            float4 v4 = *(const float4*)(qp + u * 4);
            qs[(hb + u * 4 + 0) * QS_PITCH + row] = v4.x;
            qs[(hb + u * 4 + 1) * QS_PITCH + row] = v4.y;
            qs[(hb + u * 4 + 2) * QS_PITCH + row] = v4.z;
            qs[(hb + u * 4 + 3) * QS_PITCH + row] = v4.w;
        }
    }
    {
        int row = tid >> 2;
        int hb = (tid & 3) * 16;
        const float* kp = k + (size_t)(b * SSZ + k0 + row) * DDIM + h * HD + hb;
        #pragma unroll
        for (int u = 0; u < 4; u++) {
            float4 w4 = *(const float4*)(kp + u * 4);
            ks[(hb + u * 4 + 0) * KS_PITCH + row] = w4.x;
            ks[(hb + u * 4 + 1) * KS_PITCH + row] = w4.y;
            ks[(hb + u * 4 + 2) * KS_PITCH + row] = w4.z;
            ks[(hb + u * 4 + 3) * KS_PITCH + row] = w4.w;
        }
    }
    __syncthreads();

    int tx = tid & 15, ty = tid >> 4;
    unsigned long long acc2[8][2];
    #pragma unroll
    for (int i = 0; i < 8; i++) { acc2[i][0] = 0ULL; acc2[i][1] = 0ULL; }

    #pragma unroll 8
    for (int kk = 0; kk < 64; kk++) {
        float4 a0 = *(const float4*)&qs[kk * QS_PITCH + ty * 8];
        float4 a1 = *(const float4*)&qs[kk * QS_PITCH + ty * 8 + 4];
        float af[8] = {a0.x, a0.y, a0.z, a0.w, a1.x, a1.y, a1.z, a1.w};
        ulonglong2 bb = *(const ulonglong2*)&ks[kk * KS_PITCH + tx * 4];
        unsigned long long ad[8];
        #pragma unroll
        for (int i = 0; i < 8; i++) ad[i] = dup_f32x2(af[i]);
        #pragma unroll
        for (int i = 0; i < 8; i++) {
            fma_f32x2(acc2[i][0], ad[i], bb.x);
            fma_f32x2(acc2[i][1], ad[i], bb.y);
        }
    }
    float* out = sc + (size_t)z * SSZ * SSZ;
    #pragma unroll
    for (int i = 0; i < 8; i++) {
        #pragma unroll
        for (int jp = 0; jp < 2; jp++) {
            float lo, hi;
            unpack_f32x2(acc2[i][jp], lo, hi);
            out[(size_t)(q0 + ty * 8 + i) * SSZ + k0 + tx * 4 + jp * 2]     = lo * 0.125f;
            out[(size_t)(q0 + ty * 8 + i) * SSZ + k0 + tx * 4 + jp * 2 + 1] = hi * 0.125f;
        }
    }
}

// ---------------- softmax over keys with per-(b,key) bias ----------------
__global__ void softmax_rows(float* __restrict__ sc, const float* __restrict__ kb) {
    int row = blockIdx.x;
    int b = row / (NH * SSZ);
    float* p = sc + (size_t)row * SSZ;
    const float* kbp = kb + b * SSZ;
    int tid = threadIdx.x;
    float v[4]; float mx = -3.4e38f;
    #pragma unroll
    for (int u = 0; u < 4; u++) {
        int c = u * 256 + tid;
        v[u] = p[c] + kbp[c];
        mx = fmaxf(mx, v[u]);
    }
    mx = blk_max(mx);
    float s = 0.0f;
    #pragma unroll
    for (int u = 0; u < 4; u++) { v[u] = expf(v[u] - mx); s += v[u]; }
    s = blk_sum(s);
    float inv = 1.0f / s;
    #pragma unroll
    for (int u = 0; u < 4; u++) p[u * 256 + tid] = v[u] * inv;
}

// ---------------- AV (128q x 64hd tile, 32-key chunks, FFMA2) ----------------
// Per-output chain: keys ascending 0..1023 (chunks of 32, kk inner ascending)
// — bitwise identical to R4/R12 attn_av.
__global__ void __launch_bounds__(256, 3)
attn_av(const float* __restrict__ sc, const float* __restrict__ v,
        float* __restrict__ o) {
    __shared__ float As[32][QS_PITCH];
    __shared__ float Bs[32][KS_PITCH];
    int z = blockIdx.y, b = z / NH, h = z % NH;
    int q0 = blockIdx.x * 128;
    const float* Ab = sc + (size_t)z * SSZ * SSZ;
    const float* Vb = v + (size_t)b * SSZ * DDIM + h * HD;
    int tid = threadIdx.x;
    int ar = tid >> 1, ac = (tid & 1) * 16;   // probs: 128 rows x 32 keys
    int br = tid >> 3, bc = (tid & 7) * 8;    // V: 32 keys x 64 hd
    int tx = tid & 15, ty = tid >> 4;
    unsigned long long acc2[8][2];
    #pragma unroll
    for (int i = 0; i < 8; i++) { acc2[i][0] = 0ULL; acc2[i][1] = 0ULL; }

    for (int k0 = 0; k0 < SSZ; k0 += 32) {
        const float* ap = Ab + (size_t)(q0 + ar) * SSZ + k0 + ac;
        #pragma unroll
        for (int u = 0; u < 4; u++) {
            float4 a4 = *(const float4*)(ap + u * 4);
            As[ac + u * 4 + 0][ar] = a4.x;
            As[ac + u * 4 + 1][ar] = a4.y;
            As[ac + u * 4 + 2][ar] = a4.z;
            As[ac + u * 4 + 3][ar] = a4.w;
        }
        const float* vp = Vb + (size_t)(k0 + br) * DDIM + bc;
        float4 b4 = *(const float4*)vp;
        float4 b5 = *(const float4*)(vp + 4);
        *(float4*)&Bs[br][bc]     = b4;
        *(float4*)&Bs[br][bc + 4] = b5;
        __syncthreads();
        #pragma unroll
        for (int kk = 0; kk < 32; kk++) {
            float4 a0 = *(const float4*)&As[kk][ty * 8];
            float4 a1 = *(const float4*)&As[kk][ty * 8 + 4];
            float af[8] = {a0.x, a0.y, a0.z, a0.w, a1.x, a1.y, a1.z, a1.w};
            ulonglong2 bb = *(const ulonglong2*)&Bs[kk][tx * 4];
            unsigned long long ad[8];
            #pragma unroll
            for (int i = 0; i < 8; i++) ad[i] = dup_f32x2(af[i]);
            #pragma unroll
            for (int i = 0; i < 8; i++) {
                fma_f32x2(acc2[i][0], ad[i], bb.x);
                fma_f32x2(acc2[i][1], ad[i], bb.y);
            }
        }
        __syncthreads();
    }
    float* Ob = o + (size_t)(b * SSZ + q0) * DDIM + h * HD;
    #pragma unroll
    for (int i = 0; i < 8; i++) {
        #pragma unroll
        for (int jp = 0; jp < 2; jp++) {
            float lo, hi;
            unpack_f32x2(acc2[i][jp], lo, hi);
            Ob[(size_t)(ty * 8 + i) * DDIM + tx * 4 + jp * 2]     = lo;
            Ob[(size_t)(ty * 8 + i) * DDIM + tx * 4 + jp * 2 + 1] = hi;
        }
    }
}

// ---------------- residual add + LayerNorm ----------------
__global__ void add_ln(const float* __restrict__ x, const float* __restrict__ y,
                       const float* __restrict__ g, const float* __restrict__ be,
                       float* __restrict__ out) {
    int row = blockIdx.x, tid = threadIdx.x;
    const float* xp = x + (size_t)row * DDIM;
    const float* yp = y + (size_t)row * DDIM;
    float v[4]; float s = 0.0f;
    #pragma unroll
    for (int u = 0; u < 4; u++) {
        int c = u * 256 + tid;
        v[u] = xp[c] + yp[c];
        s += v[u];
    }
    s = blk_sum(s);
    float mean = s * (1.0f / DDIM);
    float qv = 0.0f;
    #pragma unroll
    for (int u = 0; u < 4; u++) { float dd = v[u] - mean; qv += dd * dd; }
    qv = blk_sum(qv);
    float rstd = rsqrtf(qv * (1.0f / DDIM) + 1e-5f);
    float* op = out + (size_t)row * DDIM;
    #pragma unroll
    for (int u = 0; u < 4; u++) {
        int c = u * 256 + tid;
        op[c] = (v[u] - mean) * rstd * g[c] + be[c];
    }
}

// ---------------- importance score head ----------------
__global__ void score_head(const float* __restrict__ f, const float* __restrict__ Ws,
                           const float* __restrict__ bsc, const float* __restrict__ masks,
                           float* __restrict__ sv) {
    int row = blockIdx.x, tid = threadIdx.x;
    const float* fp = f + (size_t)row * DDIM;
    float s = 0.0f;
    #pragma unroll
    for (int u = 0; u < 4; u++) {
        int c = u * 256 + tid;
        s += fp[c] * Ws[c];
    }
    s = blk_sum(s);
    if (tid == 0) {
        float val = 1.0f / (1.0f + expf(-(s + bsc[0])));
        sv[row] = (masks[row] > 0.0f) ? val : 0.0f;
    }
}

__global__ void make_kb2(const float* __restrict__ masks, float* __restrict__ kb2) {
    int i = blockIdx.x * 256 + threadIdx.x;
    if (i < MTOT) kb2[i] = (masks[i] > 0.0f) ? 0.0f : -1e9f;
}

// ---------------- sequential scan per batch ----------------
__global__ void scan_kernel(const float* __restrict__ sv, const float* __restrict__ masks,
                            int* __restrict__ seg, float* __restrict__ mask_out) {
    int b = threadIdx.x;
    if (b >= BB) return;
    float c = 0.0f, maxseg = -1.0f;
    for (int t = 0; t < SSZ; t++) {
        c = c + sv[b * SSZ + t];
        float cf = floorf(c);
        int sg = (int)cf;
        if (sg > SSZ - 1) sg = SSZ - 1;
        if (sg < 0) sg = 0;
        seg[b * SSZ + t] = sg;
        if (masks[b * SSZ + t] > 0.0f) maxseg = fmaxf(maxseg, cf);
    }
    for (int t = 0; t < SSZ; t++)
        mask_out[b * SSZ + t] = ((float)t <= maxseg) ? 1.0f : 0.0f;
}

__global__ void zero_pool(float* __restrict__ p) {
    size_t i = (size_t)blockIdx.x * 256 + threadIdx.x;
    if (i < (size_t)MTOT * DDIM) p[i] = 0.0f;
}

__global__ void seg_pool(const float* __restrict__ x, const float* __restrict__ sv,
                         const int* __restrict__ seg, float* __restrict__ pooled) {
    int b = blockIdx.y;
    int dcol = blockIdx.x * 256 + threadIdx.x;
    __shared__ float svs[SSZ];
    __shared__ int sgs[SSZ];
    for (int t = threadIdx.x; t < SSZ; t += 256) {
        svs[t] = sv[b * SSZ + t];
        sgs[t] = seg[b * SSZ + t];
    }
    __syncthreads();
    const float* xb = x + (size_t)b * SSZ * DDIM + dcol;
    float acc = 0.0f;
    int cur = sgs[0];
    for (int t = 0; t < SSZ; t++) {
        int sg = sgs[t];
        if (sg != cur) {
            pooled[((size_t)b * SSZ + cur) * DDIM + dcol] = acc;
            acc = 0.0f;
            cur = sg;
        }
        acc = fmaf(xb[(size_t)t * DDIM], svs[t], acc);
    }
    pooled[((size_t)b * SSZ + cur) * DDIM + dcol] = acc;
}

// ---------------- host ----------------
extern "C" void kernel_launch(void* const* d_in, const int* in_sizes, int n_in,
                              void* d_out, int out_size) {
    const float* x     = (const float*)d_in[0];
    const float* masks = (const float*)d_in[1];
    const float* Wq = (const float*)d_in[2];  const float* bq = (const float*)d_in[3];
    const float* Wk = (const float*)d_in[4];  const float* bk = (const float*)d_in[5];
    const float* Wv = (const float*)d_in[6];  const float* bv = (const float*)d_in[7];
    const float* Wo = (const float*)d_in[8];  const float* bo = (const float*)d_in[9];
    const float* g1 = (const float*)d_in[10]; const float* be1 = (const float*)d_in[11];
    const float* g2 = (const float*)d_in[12]; const float* be2 = (const float*)d_in[13];
    const float* W1 = (const float*)d_in[14]; const float* bf1 = (const float*)d_in[15];
    const float* W2 = (const float*)d_in[16]; const float* bf2 = (const float*)d_in[17];
    const float* Ws = (const float*)d_in[18]; const float* bs = (const float*)d_in[19];
    const float* P1 = (const float*)d_in[20]; const float* bp1 = (const float*)d_in[21];
    const float* P2 = (const float*)d_in[22]; const float* bp2 = (const float*)d_in[23];
    float* out = (float*)d_out;

    float *q, *k, *v, *sc, *attn, *tmp, *h, *ffn, *feat, *feat2, *sv, *kb2, *pool, *ph;
    float *wqkv, *bqkv;
    int* seg;
    cudaGetSymbolAddress((void**)&q, g_q);
    cudaGetSymbolAddress((void**)&k, g_k);
    cudaGetSymbolAddress((void**)&v, g_v);
    cudaGetSymbolAddress((void**)&sc, g_sc);
    cudaGetSymbolAddress((void**)&attn, g_attn);
    cudaGetSymbolAddress((void**)&tmp, g_tmp);
    cudaGetSymbolAddress((void**)&h, g_h);
    cudaGetSymbolAddress((void**)&ffn, g_ffn);
    cudaGetSymbolAddress((void**)&feat, g_feat);
    cudaGetSymbolAddress((void**)&feat2, g_feat2);
    cudaGetSymbolAddress((void**)&sv, g_sv);
    cudaGetSymbolAddress((void**)&kb2, g_kb2);
    cudaGetSymbolAddress((void**)&seg, g_seg);
    cudaGetSymbolAddress((void**)&pool, g_pool);
    cudaGetSymbolAddress((void**)&ph, g_ph);
    cudaGetSymbolAddress((void**)&wqkv, g_wqkv);
    cudaGetSymbolAddress((void**)&bqkv, g_bqkv);

    const int SM2 = 2 * (GA_SZ + GB_SZ) * 2;   // 37888 bytes
    cudaFuncSetAttribute(gemm_mma<2,0>, cudaFuncAttributeMaxDynamicSharedMemorySize, SM2);
    cudaFuncSetAttribute(gemm_mma<2,1>, cudaFuncAttributeMaxDynamicSharedMemorySize, SM2);
    cudaFuncSetAttribute(attn_scores, cudaFuncAttributeMaxDynamicSharedMemorySize, SCORES_SMEM);

    concat_qkv<<<(DDIM * 3 * DDIM) / 256, 256>>>(Wq, Wk, Wv, bq, bk, bv, wqkv, bqkv);

    auto layer = [&](const float* in, const float* kb, float* outf) {
        gemm128<0,1><<<dim3(3 * DDIM / 128, MTOT / 128), 256>>>(
            in, wqkv, bqkv, q, k, v, MTOT, 3 * DDIM, DDIM);
        dim3 gs(SSZ / 64, SSZ / 128, BB * NH);
        attn_scores<<<gs, 256, SCORES_SMEM>>>(q, k, sc);
        softmax_rows<<<BB * NH * SSZ, 256>>>(sc, kb);
        dim3 ga(SSZ / 128, BB * NH);
        attn_av<<<ga, 256>>>(sc, v, attn);
        gemm128<0,0><<<dim3(DDIM / 128, MTOT / 128), 256>>>(
            attn, Wo, bo, tmp, nullptr, nullptr, MTOT, DDIM, DDIM);
        add_ln<<<MTOT, 256>>>(in, tmp, g1, be1, h);
        gemm128<1,0><<<dim3(FF / 128, MTOT / 128), 256>>>(
            h, W1, bf1, ffn, nullptr, nullptr, MTOT, FF, DDIM);
        gemm128<0,0><<<dim3(DDIM / 128, MTOT / 128), 256>>>(
            ffn, W2, bf2, tmp, nullptr, nullptr, MTOT, DDIM, FF);
        add_ln<<<MTOT, 256>>>(h, tmp, g2, be2, outf);
    };

    layer(x, masks, feat);
    make_kb2<<<MTOT / 256, 256>>>(masks, kb2);
    layer(feat, kb2, feat2);

    score_head<<<MTOT, 256>>>(feat2, Ws, bs, masks, sv);
    scan_kernel<<<1, 32>>>(sv, masks, seg, out + (size_t)MTOT * HID);
    zero_pool<<<(MTOT * DDIM) / 256, 256>>>(pool);
    seg_pool<<<dim3(DDIM / 256, BB), 256>>>(x, sv, seg, pool);

    gemm_mma<2,1><<<dim3(HID / 128, MTOT / 128), 256, SM2>>>(pool, P1, bp1, ph, MTOT, HID, DDIM);
    gemm_mma<2,0><<<dim3(HID / 128, MTOT / 128), 256, SM2>>>(ph, P2, bp2, out, MTOT, HID, HID);
}

// round 16
// speedup vs baseline: 1.3269x; 1.0117x over previous
#include <cuda_runtime.h>
#include <cuda_bf16.h>
#include <math.h>

#define BB 4
#define SSZ 1024
#define DDIM 1024
#define NH 16
#define HD 64
#define FF 2048
#define HID 4096
#define MTOT (BB*SSZ)   // 4096

// ---------------- scratch (static device globals; no allocation) ----------------
__device__ float g_q[MTOT*DDIM];
__device__ float g_k[MTOT*DDIM];
__device__ float g_v[MTOT*DDIM];
__device__ float g_sc[67108864];          // [B*NH, S, S]
__device__ float g_attn[MTOT*DDIM];
__device__ float g_tmp[MTOT*DDIM];
__device__ float g_h[MTOT*DDIM];
__device__ float g_ffn[MTOT*FF];
__device__ float g_feat[MTOT*DDIM];
__device__ float g_feat2[MTOT*DDIM];
__device__ float g_sv[MTOT];
__device__ float g_kb2[MTOT];
__device__ int   g_seg[MTOT];
__device__ float g_pool[MTOT*DDIM];
__device__ float g_wqkv[DDIM*3*DDIM];
__device__ float g_bqkv[3*DDIM];
// bf16 planes for the projector (pre-split)
__device__ __nv_bfloat16 g_P1p[2u*DDIM*HID];     // [2][K=1024][N=4096]
__device__ __nv_bfloat16 g_P2p[2u*HID*HID];      // [2][K=4096][N=4096]
__device__ __nv_bfloat16 g_poolp[2u*MTOT*DDIM];  // [2][M][K=1024]
__device__ __nv_bfloat16 g_php[2u*(size_t)MTOT*HID];  // [2][M][K=4096]

// ---------------- helpers ----------------
__device__ __forceinline__ float gelu_exact(float x) {
    return 0.5f * x * (1.0f + erff(x * 0.70710678118654752440f));
}

// packed f32x2: two independent IEEE fp32 FMAs per instruction (sm_103a FFMA2)
__device__ __forceinline__ unsigned long long dup_f32x2(float a) {
    unsigned u = __float_as_uint(a);
    unsigned long long r;
    asm("mov.b64 %0, {%1, %2};" : "=l"(r) : "r"(u), "r"(u));
    return r;
}
__device__ __forceinline__ void fma_f32x2(unsigned long long& d,
                                          unsigned long long a, unsigned long long b) {
    asm("fma.rn.f32x2 %0, %1, %2, %0;" : "+l"(d) : "l"(a), "l"(b));
}
__device__ __forceinline__ void unpack_f32x2(unsigned long long p, float& lo, float& hi) {
    unsigned ulo, uhi;
    asm("mov.b64 {%0, %1}, %2;" : "=r"(ulo), "=r"(uhi) : "l"(p));
    lo = __uint_as_float(ulo); hi = __uint_as_float(uhi);
}

__device__ __forceinline__ float blk_sum(float v) {
    __shared__ float sh[8];
    int lane = threadIdx.x & 31, w = threadIdx.x >> 5;
    #pragma unroll
    for (int o = 16; o; o >>= 1) v += __shfl_xor_sync(0xffffffffu, v, o);
    if (lane == 0) sh[w] = v;
    __syncthreads();
    if (threadIdx.x < 32) {
        float t = (lane < 8) ? sh[lane] : 0.0f;
        #pragma unroll
        for (int o = 4; o; o >>= 1) t += __shfl_xor_sync(0xffffffffu, t, o);
        if (lane == 0) sh[0] = t;
    }
    __syncthreads();
    float r = sh[0];
    __syncthreads();
    return r;
}

__device__ __forceinline__ float blk_max(float v) {
    __shared__ float sh[8];
    int lane = threadIdx.x & 31, w = threadIdx.x >> 5;
    #pragma unroll
    for (int o = 16; o; o >>= 1) v = fmaxf(v, __shfl_xor_sync(0xffffffffu, v, o));
    if (lane == 0) sh[w] = v;
    __syncthreads();
    if (threadIdx.x < 32) {
        float t = (lane < 8) ? sh[lane] : -3.4e38f;
        #pragma unroll
        for (int o = 4; o; o >>= 1) t = fmaxf(t, __shfl_xor_sync(0xffffffffu, t, o));
        if (lane == 0) sh[0] = t;
    }
    __syncthreads();
    float r = sh[0];
    __syncthreads();
    return r;
}

// ---------------- concat [Wq|Wk|Wv] and biases ----------------
__global__ void concat_qkv(const float* __restrict__ Wq, const float* __restrict__ Wk,
                           const float* __restrict__ Wv, const float* __restrict__ bq,
                           const float* __restrict__ bk, const float* __restrict__ bv,
                           float* __restrict__ Wc, float* __restrict__ bc) {
    int i = blockIdx.x * 256 + threadIdx.x;
    int r = i / 3072, c = i % 3072;
    float val;
    if (c < 1024)      val = Wq[r * 1024 + c];
    else if (c < 2048) val = Wk[r * 1024 + (c - 1024)];
    else               val = Wv[r * 1024 + (c - 2048)];
    Wc[i] = val;
    if (i < 3072)
        bc[i] = (i < 1024) ? bq[i] : (i < 2048) ? bk[i - 1024] : bv[i - 2048];
}

// ---------------- 2-plane split: in[n] fp32 -> out[2][n] bf16 ----------------
__global__ void split_planes2(const float* __restrict__ in, __nv_bfloat16* __restrict__ out,
                              size_t n) {
    size_t i = (size_t)blockIdx.x * 256 + threadIdx.x;
    if (i >= n) return;
    float r = in[i];
    __nv_bfloat16 hi = __float2bfloat16(r);
    out[i] = hi;
    out[n + i] = __float2bfloat16(r - __bfloat162float(hi));
}

// ---------------- fp32 GEMM (128x128, double-buffered, FFMA2) ----------------
// Per-output fmaf chain identical to R2/R4: k ascending, lane-independent FFMA2.
// QKV3: N==3072 with per-128-col-block routing into q/k/v (boundaries at 1024).
template<int ACT, int QKV3>
__global__ void __launch_bounds__(256, 2)
gemm128(const float* __restrict__ A, const float* __restrict__ B,
        const float* __restrict__ bias, float* __restrict__ C0,
        float* __restrict__ C1, float* __restrict__ C2,
        int M, int N, int K) {
    __shared__ float As[2][8][128];
    __shared__ float Bs[2][8][128];
    int tid = threadIdx.x;
    int col0 = blockIdx.x * 128, row0 = blockIdx.y * 128;
    int tx = tid & 15, ty = tid >> 4;
    int ar = tid >> 1, ac = (tid & 1) * 4;
    int br = tid >> 5, bc = (tid & 31) * 4;
    const float* Aptr = A + (size_t)(row0 + ar) * K + ac;
    const float* Bptr = B + (size_t)br * N + col0 + bc;
    unsigned long long acc2[8][4];
    #pragma unroll
    for (int i = 0; i < 8; i++)
        #pragma unroll
        for (int jp = 0; jp < 4; jp++) acc2[i][jp] = 0ULL;

    {
        float4 av = *(const float4*)Aptr;
        As[0][ac + 0][ar] = av.x; As[0][ac + 1][ar] = av.y;
        As[0][ac + 2][ar] = av.z; As[0][ac + 3][ar] = av.w;
        float4 bv = *(const float4*)Bptr;
        *(float4*)&Bs[0][br][bc] = bv;
    }
    __syncthreads();

    int cur = 0;
    for (int k0 = 0; k0 < K; k0 += 8) {
        bool has = (k0 + 8 < K);
        float4 av2, bv2;
        if (has) {
            av2 = *(const float4*)(Aptr + k0 + 8);
            bv2 = *(const float4*)(Bptr + (size_t)(k0 + 8) * N);
        }
        #pragma unroll
        for (int kk = 0; kk < 8; kk++) {
            float4 a0 = *(const float4*)&As[cur][kk][ty * 8];
            float4 a1 = *(const float4*)&As[cur][kk][ty * 8 + 4];
            float af[8] = {a0.x, a0.y, a0.z, a0.w, a1.x, a1.y, a1.z, a1.w};
            const ulonglong2* bp = (const ulonglong2*)&Bs[cur][kk][tx * 8];
            ulonglong2 bq0 = bp[0], bq1 = bp[1];
            unsigned long long bq[4] = {bq0.x, bq0.y, bq1.x, bq1.y};
            unsigned long long ad[8];
            #pragma unroll
            for (int i = 0; i < 8; i++) ad[i] = dup_f32x2(af[i]);
            #pragma unroll
            for (int i = 0; i < 8; i++)
                #pragma unroll
                for (int jp = 0; jp < 4; jp++)
                    fma_f32x2(acc2[i][jp], ad[i], bq[jp]);
        }
        if (has) {
            int nb = cur ^ 1;
            As[nb][ac + 0][ar] = av2.x; As[nb][ac + 1][ar] = av2.y;
            As[nb][ac + 2][ar] = av2.z; As[nb][ac + 3][ar] = av2.w;
            *(float4*)&Bs[nb][br][bc] = bv2;
        }
        __syncthreads();
        cur ^= 1;
    }

    float* Cd = C0;
    int cl0 = col0;
    int Nout = N;
    if (QKV3) {
        int seg = col0 >> 10;
        Cd = (seg == 0) ? C0 : (seg == 1) ? C1 : C2;
        cl0 = col0 & 1023;
        Nout = 1024;
    }
    #pragma unroll
    for (int i = 0; i < 8; i++) {
        int r = row0 + ty * 8 + i;
        #pragma unroll
        for (int jp = 0; jp < 4; jp++) {
            float lo, hi;
            unpack_f32x2(acc2[i][jp], lo, hi);
            int gc = col0 + tx * 8 + jp * 2;
            int c  = cl0 + tx * 8 + jp * 2;
            float v0 = lo + bias[gc];
            float v1 = hi + bias[gc + 1];
            if (ACT == 1) { v0 = gelu_exact(v0); v1 = gelu_exact(v1); }
            Cd[(size_t)r * Nout + c]     = v0;
            Cd[(size_t)r * Nout + c + 1] = v1;
        }
    }
}

// ========== plane-based bf16 tensor-core GEMM (projector; NS=2, 3 products) ====
// A planes [2][M][K], B planes [2][K][N]. WRF32: write fp32 C. OPL: write OPL
// bf16 output planes to Cp (skips fp32 round-trip for the ph intermediate).
#define GA_PAD 40
#define GB_PAD 136
#define GA_SZ (128*GA_PAD)
#define GB_SZ (32*GB_PAD)

__device__ __forceinline__ void mma16816(float* d, const unsigned* a,
                                         unsigned b0, unsigned b1) {
    asm volatile(
        "mma.sync.aligned.m16n8k16.row.col.f32.bf16.bf16.f32 "
        "{%0,%1,%2,%3}, {%4,%5,%6,%7}, {%8,%9}, {%0,%1,%2,%3};"
        : "+f"(d[0]), "+f"(d[1]), "+f"(d[2]), "+f"(d[3])
        : "r"(a[0]), "r"(a[1]), "r"(a[2]), "r"(a[3]), "r"(b0), "r"(b1));
}

__device__ __forceinline__ void ldsm4(unsigned* r, const __nv_bfloat16* p) {
    unsigned addr = (unsigned)__cvta_generic_to_shared(p);
    asm volatile("ldmatrix.sync.aligned.m8n8.x4.shared.b16 {%0,%1,%2,%3}, [%4];"
                 : "=r"(r[0]), "=r"(r[1]), "=r"(r[2]), "=r"(r[3]) : "r"(addr));
}

__device__ __forceinline__ void ldsm4t(unsigned* r, const __nv_bfloat16* p) {
    unsigned addr = (unsigned)__cvta_generic_to_shared(p);
    asm volatile("ldmatrix.sync.aligned.m8n8.x4.trans.shared.b16 {%0,%1,%2,%3}, [%4];"
                 : "=r"(r[0]), "=r"(r[1]), "=r"(r[2]), "=r"(r[3]) : "r"(addr));
}

template<int ACT, int WRF32, int OPL>
__global__ void __launch_bounds__(256, 2)
gemm_pl(const __nv_bfloat16* __restrict__ Ap, const __nv_bfloat16* __restrict__ Bp,
        const float* __restrict__ bias, float* __restrict__ C,
        __nv_bfloat16* __restrict__ Cp,
        int M, int N, int K) {
    extern __shared__ __nv_bfloat16 smbuf[];
    __nv_bfloat16* Ah = smbuf;                  // [2][128][GA_PAD]
    __nv_bfloat16* Bh = smbuf + 2 * GA_SZ;      // [2][32][GB_PAD]

    const size_t Aps = (size_t)M * K;
    const size_t Bps = (size_t)K * N;
    const size_t Cps = (size_t)M * N;

    const int tid = threadIdx.x;
    const int lane = tid & 31, w = tid >> 5;
    const int wm = w & 3, wn = w >> 2;
    const int row0 = blockIdx.y * 128, col0 = blockIdx.x * 128;

    float d[2][8][4];
    #pragma unroll
    for (int i = 0; i < 2; i++)
        #pragma unroll
        for (int j = 0; j < 8; j++)
            #pragma unroll
            for (int c = 0; c < 4; c++) d[i][j][c] = 0.0f;

    const int SA[3] = {0, 0, 1};
    const int SB[3] = {0, 1, 0};

    const int a_row = wm * 32 + (lane & 15);
    const int a_kof = (lane >> 4) << 3;
    const int b_kof = ((lane >> 3) & 1) * 8 + (lane & 7);
    const int b_nof = wn * 64 + (lane >> 4) * 8;

    // fill-thread mapping
    const int fa_m = tid >> 2, fa_k = (tid & 3) * 8;     // A: 64 rows/pass, 2 passes
    const int fb_k = tid >> 4, fb_n = (tid & 15) * 8;    // B: 16 k/pass, 2 passes

    for (int k0 = 0; k0 < K; k0 += 32) {
        #pragma unroll
        for (int s = 0; s < 2; s++) {
            const __nv_bfloat16* Ag = Ap + (size_t)s * Aps;
            #pragma unroll
            for (int pass = 0; pass < 2; pass++) {
                int m = fa_m + pass * 64;
                int4 val = *(const int4*)(Ag + (size_t)(row0 + m) * K + k0 + fa_k);
                *(int4*)(Ah + s * GA_SZ + m * GA_PAD + fa_k) = val;
            }
            const __nv_bfloat16* Bg = Bp + (size_t)s * Bps;
            #pragma unroll
            for (int pass = 0; pass < 2; pass++) {
                int kk = fb_k + pass * 16;
                int4 val = *(const int4*)(Bg + (size_t)(k0 + kk) * N + col0 + fb_n);
                *(int4*)(Bh + s * GB_SZ + kk * GB_PAD + fb_n) = val;
            }
        }
        __syncthreads();

        #pragma unroll
        for (int kk = 0; kk < 32; kk += 16) {
            unsigned afr[2][2][4];
            #pragma unroll
            for (int s = 0; s < 2; s++)
                #pragma unroll
                for (int mt = 0; mt < 2; mt++)
                    ldsm4(afr[s][mt],
                          Ah + s * GA_SZ + (a_row + mt * 16) * GA_PAD + kk + a_kof);
            #pragma unroll
            for (int nt4 = 0; nt4 < 4; nt4++) {
                unsigned bfr[2][4];
                #pragma unroll
                for (int s = 0; s < 2; s++)
                    ldsm4t(bfr[s],
                           Bh + s * GB_SZ + (kk + b_kof) * GB_PAD + b_nof + nt4 * 16);
                #pragma unroll
                for (int mt = 0; mt < 2; mt++) {
                    #pragma unroll
                    for (int c = 0; c < 3; c++) {
                        mma16816(d[mt][nt4 * 2],     afr[SA[c]][mt], bfr[SB[c]][0], bfr[SB[c]][1]);
                        mma16816(d[mt][nt4 * 2 + 1], afr[SA[c]][mt], bfr[SB[c]][2], bfr[SB[c]][3]);
                    }
                }
            }
        }
        __syncthreads();
    }

    const int g = lane >> 2, l = lane & 3;
    #pragma unroll
    for (int mt = 0; mt < 2; mt++) {
        int rbase = row0 + wm * 32 + mt * 16 + g;
        #pragma unroll
        for (int nt = 0; nt < 8; nt++) {
            int c = col0 + wn * 64 + nt * 8 + 2 * l;
            float bia0 = bias[c], bia1 = bias[c + 1];
            float vv[2][2] = {{d[mt][nt][0] + bia0, d[mt][nt][1] + bia1},
                              {d[mt][nt][2] + bia0, d[mt][nt][3] + bia1}};
            #pragma unroll
            for (int rr = 0; rr < 2; rr++) {
                int r = rbase + rr * 8;
                float v0 = vv[rr][0], v1 = vv[rr][1];
                if (ACT == 1) { v0 = gelu_exact(v0); v1 = gelu_exact(v1); }
                size_t idx = (size_t)r * N + c;
                if (WRF32) {
                    float2 p = {v0, v1};
                    *(float2*)(C + idx) = p;
                }
                if (OPL > 0) {
                    __nv_bfloat162 ph0;
                    ph0.x = __float2bfloat16(v0);
                    ph0.y = __float2bfloat16(v1);
                    *(__nv_bfloat162*)(Cp + idx) = ph0;
                    if (OPL > 1) {
                        __nv_bfloat162 pl;
                        pl.x = __float2bfloat16(v0 - __bfloat162float(ph0.x));
                        pl.y = __float2bfloat16(v1 - __bfloat162float(ph0.y));
                        *(__nv_bfloat162*)(Cp + Cps + idx) = pl;
                    }
                }
            }
        }
    }
}

// ---------------- attention scores (128q x 64k tile, 8x4/thread, FFMA2) -------
#define QS_PITCH 136
#define KS_PITCH 68
#define SCORES_SMEM ((64*QS_PITCH + 64*KS_PITCH) * 4)

__global__ void __launch_bounds__(256, 3)
attn_scores(const float* __restrict__ q, const float* __restrict__ k,
            float* __restrict__ sc) {
    extern __shared__ float smf[];
    float* qs = smf;
    float* ks = smf + 64 * QS_PITCH;

    int z = blockIdx.z, b = z / NH, h = z % NH;
    int k0 = blockIdx.x * 64, q0 = blockIdx.y * 128;
    int tid = threadIdx.x;

    {
        int row = tid >> 1;
        int hb = (tid & 1) * 32;
        const float* qp = q + (size_t)(b * SSZ + q0 + row) * DDIM + h * HD + hb;
        #pragma unroll
        for (int u = 0; u < 8; u++) {
            float4 v4 = *(const float4*)(qp + u * 4);
            qs[(hb + u * 4 + 0) * QS_PITCH + row] = v4.x;
            qs[(hb + u * 4 + 1) * QS_PITCH + row] = v4.y;
            qs[(hb + u * 4 + 2) * QS_PITCH + row] = v4.z;
            qs[(hb + u * 4 + 3) * QS_PITCH + row] = v4.w;
        }
    }
    {
        int row = tid >> 2;
        int hb = (tid & 3) * 16;
        const float* kp = k + (size_t)(b * SSZ + k0 + row) * DDIM + h * HD + hb;
        #pragma unroll
        for (int u = 0; u < 4; u++) {
            float4 w4 = *(const float4*)(kp + u * 4);
            ks[(hb + u * 4 + 0) * KS_PITCH + row] = w4.x;
            ks[(hb + u * 4 + 1) * KS_PITCH + row] = w4.y;
            ks[(hb + u * 4 + 2) * KS_PITCH + row] = w4.z;
            ks[(hb + u * 4 + 3) * KS_PITCH + row] = w4.w;
        }
    }
    __syncthreads();

    int tx = tid & 15, ty = tid >> 4;
    unsigned long long acc2[8][2];
    #pragma unroll
    for (int i = 0; i < 8; i++) { acc2[i][0] = 0ULL; acc2[i][1] = 0ULL; }

    #pragma unroll 8
    for (int kk = 0; kk < 64; kk++) {
        float4 a0 = *(const float4*)&qs[kk * QS_PITCH + ty * 8];
        float4 a1 = *(const float4*)&qs[kk * QS_PITCH + ty * 8 + 4];
        float af[8] = {a0.x, a0.y, a0.z, a0.w, a1.x, a1.y, a1.z, a1.w};
        ulonglong2 bb = *(const ulonglong2*)&ks[kk * KS_PITCH + tx * 4];
        unsigned long long ad[8];
        #pragma unroll
        for (int i = 0; i < 8; i++) ad[i] = dup_f32x2(af[i]);
        #pragma unroll
        for (int i = 0; i < 8; i++) {
            fma_f32x2(acc2[i][0], ad[i], bb.x);
            fma_f32x2(acc2[i][1], ad[i], bb.y);
        }
    }
    float* out = sc + (size_t)z * SSZ * SSZ;
    #pragma unroll
    for (int i = 0; i < 8; i++) {
        #pragma unroll
        for (int jp = 0; jp < 2; jp++) {
            float lo, hi;
            unpack_f32x2(acc2[i][jp], lo, hi);
            out[(size_t)(q0 + ty * 8 + i) * SSZ + k0 + tx * 4 + jp * 2]     = lo * 0.125f;
            out[(size_t)(q0 + ty * 8 + i) * SSZ + k0 + tx * 4 + jp * 2 + 1] = hi * 0.125f;
        }
    }
}

// ---------------- softmax over keys with per-(b,key) bias ----------------
__global__ void softmax_rows(float* __restrict__ sc, const float* __restrict__ kb) {
    int row = blockIdx.x;
    int b = row / (NH * SSZ);
    float* p = sc + (size_t)row * SSZ;
    const float* kbp = kb + b * SSZ;
    int tid = threadIdx.x;
    float v[4]; float mx = -3.4e38f;
    #pragma unroll
    for (int u = 0; u < 4; u++) {
        int c = u * 256 + tid;
        v[u] = p[c] + kbp[c];
        mx = fmaxf(mx, v[u]);
    }
    mx = blk_max(mx);
    float s = 0.0f;
    #pragma unroll
    for (int u = 0; u < 4; u++) { v[u] = expf(v[u] - mx); s += v[u]; }
    s = blk_sum(s);
    float inv = 1.0f / s;
    #pragma unroll
    for (int u = 0; u < 4; u++) p[u * 256 + tid] = v[u] * inv;
}

// ---------------- AV (128q x 64hd tile, 32-key chunks, FFMA2) ----------------
__global__ void __launch_bounds__(256, 3)
attn_av(const float* __restrict__ sc, const float* __restrict__ v,
        float* __restrict__ o) {
    __shared__ float As[32][QS_PITCH];
    __shared__ float Bs[32][KS_PITCH];
    int z = blockIdx.y, b = z / NH, h = z % NH;
    int q0 = blockIdx.x * 128;
    const float* Ab = sc + (size_t)z * SSZ * SSZ;
    const float* Vb = v + (size_t)b * SSZ * DDIM + h * HD;
    int tid = threadIdx.x;
    int ar = tid >> 1, ac = (tid & 1) * 16;
    int br = tid >> 3, bc = (tid & 7) * 8;
    int tx = tid & 15, ty = tid >> 4;
    unsigned long long acc2[8][2];
    #pragma unroll
    for (int i = 0; i < 8; i++) { acc2[i][0] = 0ULL; acc2[i][1] = 0ULL; }

    for (int k0 = 0; k0 < SSZ; k0 += 32) {
        const float* ap = Ab + (size_t)(q0 + ar) * SSZ + k0 + ac;
        #pragma unroll
        for (int u = 0; u < 4; u++) {
            float4 a4 = *(const float4*)(ap + u * 4);
            As[ac + u * 4 + 0][ar] = a4.x;
            As[ac + u * 4 + 1][ar] = a4.y;
            As[ac + u * 4 + 2][ar] = a4.z;
            As[ac + u * 4 + 3][ar] = a4.w;
        }
        const float* vp = Vb + (size_t)(k0 + br) * DDIM + bc;
        float4 b4 = *(const float4*)vp;
        float4 b5 = *(const float4*)(vp + 4);
        *(float4*)&Bs[br][bc]     = b4;
        *(float4*)&Bs[br][bc + 4] = b5;
        __syncthreads();
        #pragma unroll
        for (int kk = 0; kk < 32; kk++) {
            float4 a0 = *(const float4*)&As[kk][ty * 8];
            float4 a1 = *(const float4*)&As[kk][ty * 8 + 4];
            float af[8] = {a0.x, a0.y, a0.z, a0.w, a1.x, a1.y, a1.z, a1.w};
            ulonglong2 bb = *(const ulonglong2*)&Bs[kk][tx * 4];
            unsigned long long ad[8];
            #pragma unroll
            for (int i = 0; i < 8; i++) ad[i] = dup_f32x2(af[i]);
            #pragma unroll
            for (int i = 0; i < 8; i++) {
                fma_f32x2(acc2[i][0], ad[i], bb.x);
                fma_f32x2(acc2[i][1], ad[i], bb.y);
            }
        }
        __syncthreads();
    }
    float* Ob = o + (size_t)(b * SSZ + q0) * DDIM + h * HD;
    #pragma unroll
    for (int i = 0; i < 8; i++) {
        #pragma unroll
        for (int jp = 0; jp < 2; jp++) {
            float lo, hi;
            unpack_f32x2(acc2[i][jp], lo, hi);
            Ob[(size_t)(ty * 8 + i) * DDIM + tx * 4 + jp * 2]     = lo;
            Ob[(size_t)(ty * 8 + i) * DDIM + tx * 4 + jp * 2 + 1] = hi;
        }
    }
}

// ---------------- residual add + LayerNorm ----------------
__global__ void add_ln(const float* __restrict__ x, const float* __restrict__ y,
                       const float* __restrict__ g, const float* __restrict__ be,
                       float* __restrict__ out) {
    int row = blockIdx.x, tid = threadIdx.x;
    const float* xp = x + (size_t)row * DDIM;
    const float* yp = y + (size_t)row * DDIM;
    float v[4]; float s = 0.0f;
    #pragma unroll
    for (int u = 0; u < 4; u++) {
        int c = u * 256 + tid;
        v[u] = xp[c] + yp[c];
        s += v[u];
    }
    s = blk_sum(s);
    float mean = s * (1.0f / DDIM);
    float qv = 0.0f;
    #pragma unroll
    for (int u = 0; u < 4; u++) { float dd = v[u] - mean; qv += dd * dd; }
    qv = blk_sum(qv);
    float rstd = rsqrtf(qv * (1.0f / DDIM) + 1e-5f);
    float* op = out + (size_t)row * DDIM;
    #pragma unroll
    for (int u = 0; u < 4; u++) {
        int c = u * 256 + tid;
        op[c] = (v[u] - mean) * rstd * g[c] + be[c];
    }
}

// ---------------- importance score head ----------------
__global__ void score_head(const float* __restrict__ f, const float* __restrict__ Ws,
                           const float* __restrict__ bsc, const float* __restrict__ masks,
                           float* __restrict__ sv) {
    int row = blockIdx.x, tid = threadIdx.x;
    const float* fp = f + (size_t)row * DDIM;
    float s = 0.0f;
    #pragma unroll
    for (int u = 0; u < 4; u++) {
        int c = u * 256 + tid;
        s += fp[c] * Ws[c];
    }
    s = blk_sum(s);
    if (tid == 0) {
        float val = 1.0f / (1.0f + expf(-(s + bsc[0])));
        sv[row] = (masks[row] > 0.0f) ? val : 0.0f;
    }
}

__global__ void make_kb2(const float* __restrict__ masks, float* __restrict__ kb2) {
    int i = blockIdx.x * 256 + threadIdx.x;
    if (i < MTOT) kb2[i] = (masks[i] > 0.0f) ? 0.0f : -1e9f;
}

// ---------------- sequential scan per batch ----------------
__global__ void scan_kernel(const float* __restrict__ sv, const float* __restrict__ masks,
                            int* __restrict__ seg, float* __restrict__ mask_out) {
    int b = threadIdx.x;
    if (b >= BB) return;
    float c = 0.0f, maxseg = -1.0f;
    for (int t = 0; t < SSZ; t++) {
        c = c + sv[b * SSZ + t];
        float cf = floorf(c);
        int sg = (int)cf;
        if (sg > SSZ - 1) sg = SSZ - 1;
        if (sg < 0) sg = 0;
        seg[b * SSZ + t] = sg;
        if (masks[b * SSZ + t] > 0.0f) maxseg = fmaxf(maxseg, cf);
    }
    for (int t = 0; t < SSZ; t++)
        mask_out[b * SSZ + t] = ((float)t <= maxseg) ? 1.0f : 0.0f;
}

__global__ void zero_pool(float* __restrict__ p) {
    size_t i = (size_t)blockIdx.x * 256 + threadIdx.x;
    if (i < (size_t)MTOT * DDIM) p[i] = 0.0f;
}

__global__ void seg_pool(const float* __restrict__ x, const float* __restrict__ sv,
                         const int* __restrict__ seg, float* __restrict__ pooled) {
    int b = blockIdx.y;
    int dcol = blockIdx.x * 256 + threadIdx.x;
    __shared__ float svs[SSZ];
    __shared__ int sgs[SSZ];
    for (int t = threadIdx.x; t < SSZ; t += 256) {
        svs[t] = sv[b * SSZ + t];
        sgs[t] = seg[b * SSZ + t];
    }
    __syncthreads();
    const float* xb = x + (size_t)b * SSZ * DDIM + dcol;
    float acc = 0.0f;
    int cur = sgs[0];
    for (int t = 0; t < SSZ; t++) {
        int sg = sgs[t];
        if (sg != cur) {
            pooled[((size_t)b * SSZ + cur) * DDIM + dcol] = acc;
            acc = 0.0f;
            cur = sg;
        }
        acc = fmaf(xb[(size_t)t * DDIM], svs[t], acc);
    }
    pooled[((size_t)b * SSZ + cur) * DDIM + dcol] = acc;
}

// ---------------- host ----------------
extern "C" void kernel_launch(void* const* d_in, const int* in_sizes, int n_in,
                              void* d_out, int out_size) {
    const float* x     = (const float*)d_in[0];
    const float* masks = (const float*)d_in[1];
    const float* Wq = (const float*)d_in[2];  const float* bq = (const float*)d_in[3];
    const float* Wk = (const float*)d_in[4];  const float* bk = (const float*)d_in[5];
    const float* Wv = (const float*)d_in[6];  const float* bv = (const float*)d_in[7];
    const float* Wo = (const float*)d_in[8];  const float* bo = (const float*)d_in[9];
    const float* g1 = (const float*)d_in[10]; const float* be1 = (const float*)d_in[11];
    const float* g2 = (const float*)d_in[12]; const float* be2 = (const float*)d_in[13];
    const float* W1 = (const float*)d_in[14]; const float* bf1 = (const float*)d_in[15];
    const float* W2 = (const float*)d_in[16]; const float* bf2 = (const float*)d_in[17];
    const float* Ws = (const float*)d_in[18]; const float* bs = (const float*)d_in[19];
    const float* P1 = (const float*)d_in[20]; const float* bp1 = (const float*)d_in[21];
    const float* P2 = (const float*)d_in[22]; const float* bp2 = (const float*)d_in[23];
    float* out = (float*)d_out;

    float *q, *k, *v, *sc, *attn, *tmp, *h, *ffn, *feat, *feat2, *sv, *kb2, *pool;
    float *wqkv, *bqkv;
    __nv_bfloat16 *P1p, *P2p, *poolp, *php;
    int* seg;
    cudaGetSymbolAddress((void**)&q, g_q);
    cudaGetSymbolAddress((void**)&k, g_k);
    cudaGetSymbolAddress((void**)&v, g_v);
    cudaGetSymbolAddress((void**)&sc, g_sc);
    cudaGetSymbolAddress((void**)&attn, g_attn);
    cudaGetSymbolAddress((void**)&tmp, g_tmp);
    cudaGetSymbolAddress((void**)&h, g_h);
    cudaGetSymbolAddress((void**)&ffn, g_ffn);
    cudaGetSymbolAddress((void**)&feat, g_feat);
    cudaGetSymbolAddress((void**)&feat2, g_feat2);
    cudaGetSymbolAddress((void**)&sv, g_sv);
    cudaGetSymbolAddress((void**)&kb2, g_kb2);
    cudaGetSymbolAddress((void**)&seg, g_seg);
    cudaGetSymbolAddress((void**)&pool, g_pool);
    cudaGetSymbolAddress((void**)&wqkv, g_wqkv);
    cudaGetSymbolAddress((void**)&bqkv, g_bqkv);
    cudaGetSymbolAddress((void**)&P1p, g_P1p);
    cudaGetSymbolAddress((void**)&P2p, g_P2p);
    cudaGetSymbolAddress((void**)&poolp, g_poolp);
    cudaGetSymbolAddress((void**)&php, g_php);

    const int SM2 = 2 * (GA_SZ + GB_SZ) * 2;   // 37888 bytes
    cudaFuncSetAttribute((gemm_pl<1,0,2>), cudaFuncAttributeMaxDynamicSharedMemorySize, SM2);
    cudaFuncSetAttribute((gemm_pl<0,1,0>), cudaFuncAttributeMaxDynamicSharedMemorySize, SM2);
    cudaFuncSetAttribute(attn_scores, cudaFuncAttributeMaxDynamicSharedMemorySize, SCORES_SMEM);

    concat_qkv<<<(DDIM * 3 * DDIM) / 256, 256>>>(Wq, Wk, Wv, bq, bk, bv, wqkv, bqkv);
    // one-time projector weight splits
    split_planes2<<<(unsigned)(((size_t)DDIM * HID + 255) / 256), 256>>>(
        P1, P1p, (size_t)DDIM * HID);
    split_planes2<<<(unsigned)(((size_t)HID * HID + 255) / 256), 256>>>(
        P2, P2p, (size_t)HID * HID);

    auto layer = [&](const float* in, const float* kb, float* outf) {
        gemm128<0,1><<<dim3(3 * DDIM / 128, MTOT / 128), 256>>>(
            in, wqkv, bqkv, q, k, v, MTOT, 3 * DDIM, DDIM);
        dim3 gs(SSZ / 64, SSZ / 128, BB * NH);
        attn_scores<<<gs, 256, SCORES_SMEM>>>(q, k, sc);
        softmax_rows<<<BB * NH * SSZ, 256>>>(sc, kb);
        dim3 ga(SSZ / 128, BB * NH);
        attn_av<<<ga, 256>>>(sc, v, attn);
        gemm128<0,0><<<dim3(DDIM / 128, MTOT / 128), 256>>>(
            attn, Wo, bo, tmp, nullptr, nullptr, MTOT, DDIM, DDIM);
        add_ln<<<MTOT, 256>>>(in, tmp, g1, be1, h);
        gemm128<1,0><<<dim3(FF / 128, MTOT / 128), 256>>>(
            h, W1, bf1, ffn, nullptr, nullptr, MTOT, FF, DDIM);
        gemm128<0,0><<<dim3(DDIM / 128, MTOT / 128), 256>>>(
            ffn, W2, bf2, tmp, nullptr, nullptr, MTOT, DDIM, FF);
        add_ln<<<MTOT, 256>>>(h, tmp, g2, be2, outf);
    };

    layer(x, masks, feat);
    make_kb2<<<MTOT / 256, 256>>>(masks, kb2);
    layer(feat, kb2, feat2);

    score_head<<<MTOT, 256>>>(feat2, Ws, bs, masks, sv);
    scan_kernel<<<1, 32>>>(sv, masks, seg, out + (size_t)MTOT * HID);
    zero_pool<<<(MTOT * DDIM) / 256, 256>>>(pool);
    seg_pool<<<dim3(DDIM / 256, BB), 256>>>(x, sv, seg, pool);

    // projector: split pool once, MMA with plane outputs for ph, final fp32 out
    split_planes2<<<(unsigned)(((size_t)MTOT * DDIM + 255) / 256), 256>>>(
        pool, poolp, (size_t)MTOT * DDIM);
    gemm_pl<1,0,2><<<dim3(HID / 128, MTOT / 128), 256, SM2>>>(
        poolp, P1p, bp1, nullptr, php, MTOT, HID, DDIM);
    gemm_pl<0,1,0><<<dim3(HID / 128, MTOT / 128), 256, SM2>>>(
        php, P2p, bp2, out, nullptr, MTOT, HID, HID);
}